// round 2
// baseline (speedup 1.0000x reference)
#include <cuda_runtime.h>
#include <cstdint>
#include <cstddef>

// ---------------- problem constants ----------------
#define B_WIN 4096
#define N_TOK 49
#define CH    512
#define NH    16
#define HD    32
#define M_ROWS (B_WIN * N_TOK)      // 200704
#define QKV_N  (3 * CH)             // 1536

// ---------------- scratch (static device globals; alloc-free rule) ----------
__device__ float g_q[(long long)B_WIN * NH * N_TOK * HD];     // [B,H,N,hd]
__device__ float g_k[(long long)B_WIN * NH * N_TOK * HD];
__device__ float g_v[(long long)B_WIN * NH * N_TOK * HD];
__device__ float g_attn[(long long)M_ROWS * CH];              // [B,N,C]

// ---------------- small PTX helpers ----------------
__device__ __forceinline__ uint32_t f2tf32(float x) {
    uint32_t r;
    asm("cvt.rna.tf32.f32 %0, %1;" : "=r"(r) : "f"(x));
    return r;
}

__device__ __forceinline__ void mma_tf32(float c[4], const uint32_t a[4], const uint32_t b[2]) {
    asm volatile(
        "mma.sync.aligned.m16n8k8.row.col.f32.tf32.tf32.f32 "
        "{%0,%1,%2,%3}, {%4,%5,%6,%7}, {%8,%9}, {%0,%1,%2,%3};\n"
        : "+f"(c[0]), "+f"(c[1]), "+f"(c[2]), "+f"(c[3])
        : "r"(a[0]), "r"(a[1]), "r"(a[2]), "r"(a[3]),
          "r"(b[0]), "r"(b[1]));
}

__device__ __forceinline__ void cp_async16(void* smem, const void* gmem) {
    uint32_t s = (uint32_t)__cvta_generic_to_shared(smem);
    asm volatile("cp.async.cg.shared.global [%0], [%1], 16;\n" :: "r"(s), "l"(gmem));
}
__device__ __forceinline__ void cp_commit() { asm volatile("cp.async.commit_group;\n" ::: "memory"); }
__device__ __forceinline__ void cp_wait1()  { asm volatile("cp.async.wait_group 1;\n" ::: "memory"); }
__device__ __forceinline__ void cp_wait0()  { asm volatile("cp.async.wait_group 0;\n" ::: "memory"); }

// ---------------- GEMM: C[M,N] = A[M,K] * B[K,N] + bias[N] -----------------
// BM=128, BN=128, BK=16, 256 threads (8 warps = 2x4), warp tile 64x32 (4x4 m16n8k8)
// EPI==0: scatter qkv into g_q/g_k/g_v.   EPI==1: row-major store to Cout.
#define BM 128
#define BN 128
#define BK 16
#define AS_STRIDE 20      // conflict-free for A-fragment loads
#define BS_STRIDE 136     // conflict-free for B-fragment loads

template<int EPI>
__global__ __launch_bounds__(256, 1)
void gemm_tf32_kernel(const float* __restrict__ A, const float* __restrict__ Bw,
                      const float* __restrict__ bias, float* __restrict__ Cout,
                      int K, int N)
{
    __shared__ float As[2][BM * AS_STRIDE];
    __shared__ float Bs[2][BK * BS_STRIDE];

    if (EPI == 1) A = g_attn;

    const int tid  = threadIdx.x;
    const int lane = tid & 31;
    const int warp = tid >> 5;
    const int wm   = warp >> 2;      // 0..1
    const int wn   = warp & 3;       // 0..3
    const int bm   = blockIdx.y * BM;
    const int bn   = blockIdx.x * BN;
    const int grp  = lane >> 2;      // groupID
    const int tig  = lane & 3;       // thread-in-group

    float acc[4][4][4];
    #pragma unroll
    for (int mt = 0; mt < 4; mt++)
        #pragma unroll
        for (int nt = 0; nt < 4; nt++)
            #pragma unroll
            for (int r = 0; r < 4; r++) acc[mt][nt][r] = 0.0f;

    auto load_stage = [&](int kt, int s) {
        #pragma unroll
        for (int it = 0; it < 2; it++) {
            int L   = tid + it * 256;
            int row = L >> 2;
            int c4  = (L & 3) << 2;
            cp_async16(&As[s][row * AS_STRIDE + c4],
                       &A[(size_t)(bm + row) * K + kt * BK + c4]);
        }
        #pragma unroll
        for (int it = 0; it < 2; it++) {
            int L  = tid + it * 256;
            int kr = L >> 5;
            int c4 = (L & 31) << 2;
            cp_async16(&Bs[s][kr * BS_STRIDE + c4],
                       &Bw[(size_t)(kt * BK + kr) * N + bn + c4]);
        }
    };

    load_stage(0, 0);
    cp_commit();

    const int KT = K / BK;
    for (int kt = 0; kt < KT; kt++) {
        if (kt + 1 < KT) {
            load_stage(kt + 1, (kt + 1) & 1);
            cp_commit();
            cp_wait1();
        } else {
            cp_wait0();
        }
        __syncthreads();

        const int s = kt & 1;
        #pragma unroll
        for (int ks = 0; ks < 2; ks++) {
            const int k0 = ks * 8;
            uint32_t af[4][4], bf[4][2];
            #pragma unroll
            for (int mt = 0; mt < 4; mt++) {
                int r = wm * 64 + mt * 16 + grp;
                af[mt][0] = f2tf32(As[s][(r    ) * AS_STRIDE + k0 + tig    ]);
                af[mt][1] = f2tf32(As[s][(r + 8) * AS_STRIDE + k0 + tig    ]);
                af[mt][2] = f2tf32(As[s][(r    ) * AS_STRIDE + k0 + tig + 4]);
                af[mt][3] = f2tf32(As[s][(r + 8) * AS_STRIDE + k0 + tig + 4]);
            }
            #pragma unroll
            for (int nt = 0; nt < 4; nt++) {
                int c = wn * 32 + nt * 8 + grp;
                bf[nt][0] = f2tf32(Bs[s][(k0 + tig    ) * BS_STRIDE + c]);
                bf[nt][1] = f2tf32(Bs[s][(k0 + tig + 4) * BS_STRIDE + c]);
            }
            #pragma unroll
            for (int mt = 0; mt < 4; mt++)
                #pragma unroll
                for (int nt = 0; nt < 4; nt++)
                    mma_tf32(acc[mt][nt], af[mt], bf[nt]);
        }
        __syncthreads();
    }

    // -------- epilogue --------
    #pragma unroll
    for (int mt = 0; mt < 4; mt++) {
        #pragma unroll
        for (int rr = 0; rr < 2; rr++) {          // row half (reg>>1)
            int row = bm + wm * 64 + mt * 16 + grp + rr * 8;
            int b   = row / N_TOK;
            int n   = row - b * N_TOK;
            #pragma unroll
            for (int nt = 0; nt < 4; nt++) {
                #pragma unroll
                for (int cc = 0; cc < 2; cc++) {  // col lsb (reg&1)
                    int col = bn + wn * 32 + nt * 8 + (tig << 1) + cc;
                    float v = acc[mt][nt][rr * 2 + cc] + bias[col];
                    if (EPI == 0) {
                        int which = col >> 9;
                        int h     = (col >> 5) & 15;
                        int d     = col & 31;
                        float* dst = (which == 0) ? g_q : ((which == 1) ? g_k : g_v);
                        dst[((((size_t)b * NH + h) * N_TOK) + n) * HD + d] = v;
                    } else {
                        Cout[(size_t)row * N + col] = v;
                    }
                }
            }
        }
    }
}

// ---------------- attention kernel: one block per (window, head) -----------
// 64 threads. S = Q K^T * scale + relbias, softmax, O = P V.
// Interleaved row ownership n = ti + 7*i avoids smem bank collisions.
#define QS_STRIDE 36
#define SS_STRIDE 57

__global__ __launch_bounds__(64, 1)
void attn_kernel(const float* __restrict__ bias_table)
{
    const int h = blockIdx.x;     // 0..15
    const int w = blockIdx.y;     // 0..4095
    const int t = threadIdx.x;

    __shared__ float qs[56 * QS_STRIDE];
    __shared__ float ks2[56 * QS_STRIDE];
    __shared__ float vs[56 * QS_STRIDE];
    __shared__ float ss[56 * SS_STRIDE];
    __shared__ float bs[169];

    // relative-position bias slice for this head
    for (int i = t; i < 169; i += 64) bs[i] = bias_table[i * NH + h];

    // load Q,K,V tiles (each (w,h): 49x32 contiguous floats)
    const size_t base = ((size_t)w * NH + h) * (N_TOK * HD);
    const float4* q4 = (const float4*)(g_q + base);
    const float4* k4 = (const float4*)(g_k + base);
    const float4* v4 = (const float4*)(g_v + base);
    for (int f = t; f < (N_TOK * HD) / 4; f += 64) {       // 392 float4
        int n  = f >> 3;
        int c4 = (f & 7) << 2;
        *(float4*)&qs [n * QS_STRIDE + c4] = q4[f];
        *(float4*)&ks2[n * QS_STRIDE + c4] = k4[f];
        *(float4*)&vs [n * QS_STRIDE + c4] = v4[f];
    }
    // zero pad rows 49..55
    for (int f = t; f < 56; f += 64) {                      // 7 rows * 8 float4
        int n  = 49 + (f >> 3);
        int c4 = (f & 7) << 2;
        float4 z = make_float4(0.f, 0.f, 0.f, 0.f);
        *(float4*)&qs [n * QS_STRIDE + c4] = z;
        *(float4*)&ks2[n * QS_STRIDE + c4] = z;
        *(float4*)&vs [n * QS_STRIDE + c4] = z;
    }
    __syncthreads();

    // ---- S = Q K^T (8x8 register tile per thread; 49 threads active) ----
    if (t < 49) {
        const int ti = t / 7;
        const int tj = t % 7;
        float a[8][8];
        #pragma unroll
        for (int i = 0; i < 8; i++)
            #pragma unroll
            for (int j = 0; j < 8; j++) a[i][j] = 0.f;

        #pragma unroll
        for (int kk = 0; kk < 8; kk++) {
            float4 kv[8];
            #pragma unroll
            for (int j = 0; j < 8; j++)
                kv[j] = *(const float4*)&ks2[(tj + 7 * j) * QS_STRIDE + kk * 4];
            #pragma unroll
            for (int i = 0; i < 8; i++) {
                float4 qv = *(const float4*)&qs[(ti + 7 * i) * QS_STRIDE + kk * 4];
                #pragma unroll
                for (int j = 0; j < 8; j++) {
                    a[i][j] += qv.x * kv[j].x;
                    a[i][j] += qv.y * kv[j].y;
                    a[i][j] += qv.z * kv[j].z;
                    a[i][j] += qv.w * kv[j].w;
                }
            }
        }
        const float scale = 0.04419417382415922f;   // 512^-0.5 (full C, per source)
        #pragma unroll
        for (int i = 0; i < 8; i++) {
            int n = ti + 7 * i;                     // n/7 == i, n%7 == ti
            #pragma unroll
            for (int j = 0; j < 8; j++) {
                int m = tj + 7 * j;
                float v = a[i][j] * scale;
                if (n < 49 && m < 49)
                    v += bs[(i - j + 6) * 13 + (ti - tj + 6)];
                ss[n * SS_STRIDE + m] = v;
            }
        }
    }
    __syncthreads();

    // ---- row softmax (cols >= 49 excluded, then zeroed) ----
    if (t < 49) {
        float mx = -1e30f;
        for (int m = 0; m < 49; m++) mx = fmaxf(mx, ss[t * SS_STRIDE + m]);
        float sum = 0.f;
        for (int m = 0; m < 49; m++) {
            float e = __expf(ss[t * SS_STRIDE + m] - mx);
            sum += e;
            ss[t * SS_STRIDE + m] = e;
        }
        float inv = 1.f / sum;
        for (int m = 0; m < 49; m++) ss[t * SS_STRIDE + m] *= inv;
        for (int m = 49; m < 56; m++) ss[t * SS_STRIDE + m] = 0.f;
    }
    __syncthreads();

    // ---- O = P V (8 rows x 4 cols per thread; 56 threads active) ----
    if (t < 56) {
        const int ti = t >> 3;          // 0..6
        const int tc = t & 7;           // 0..7 -> cols d = 4*tc
        float4 o[8];
        #pragma unroll
        for (int i = 0; i < 8; i++) o[i] = make_float4(0.f, 0.f, 0.f, 0.f);

        for (int m = 0; m < 56; m++) {
            float4 vv = *(const float4*)&vs[m * QS_STRIDE + tc * 4];
            #pragma unroll
            for (int i = 0; i < 8; i++) {
                float p = ss[(ti + 7 * i) * SS_STRIDE + m];
                o[i].x += p * vv.x;
                o[i].y += p * vv.y;
                o[i].z += p * vv.z;
                o[i].w += p * vv.w;
            }
        }
        #pragma unroll
        for (int i = 0; i < 8; i++) {
            int n = ti + 7 * i;
            if (n < 49) {
                size_t off = ((size_t)w * N_TOK + n) * CH + h * HD + tc * 4;
                *(float4*)&g_attn[off] = o[i];
            }
        }
    }
}

// ---------------- launch ----------------
extern "C" void kernel_launch(void* const* d_in, const int* in_sizes, int n_in,
                              void* d_out, int out_size)
{
    const float* x          = (const float*)d_in[0];
    const float* w_qkv      = (const float*)d_in[1];
    const float* b_qkv      = (const float*)d_in[2];
    const float* w_proj     = (const float*)d_in[3];
    const float* b_proj     = (const float*)d_in[4];
    const float* bias_table = (const float*)d_in[5];
    float* out = (float*)d_out;

    // K1: qkv = x @ w_qkv + b_qkv  -> scatter to g_q/g_k/g_v
    gemm_tf32_kernel<0><<<dim3(QKV_N / BN, M_ROWS / BM), 256>>>(
        x, w_qkv, b_qkv, nullptr, CH, QKV_N);

    // K2: windowed attention -> g_attn [B,N,C]
    attn_kernel<<<dim3(NH, B_WIN), 64>>>(bias_table);

    // K3: out = g_attn @ w_proj + b_proj
    gemm_tf32_kernel<1><<<dim3(CH / BN, M_ROWS / BM), 256>>>(
        nullptr, w_proj, b_proj, out, CH, CH);
}

// round 4
// speedup vs baseline: 1.4473x; 1.4473x over previous
#include <cuda_runtime.h>
#include <cuda_fp16.h>
#include <cstdint>
#include <cstddef>

// ---------------- problem constants ----------------
#define B_WIN 4096
#define N_TOK 49
#define CH    512
#define NH    16
#define HD    32
#define M_ROWS (B_WIN * N_TOK)      // 200704
#define QKV_N  (3 * CH)             // 1536

// ---------------- scratch (static device globals; alloc-free rule) ----------
__device__ __half g_xh   [(long long)M_ROWS * CH];            // x in fp16
__device__ __half g_q    [(long long)B_WIN * NH * N_TOK * HD];// [B,H,N,hd] fp16
__device__ __half g_k    [(long long)B_WIN * NH * N_TOK * HD];
__device__ __half g_v    [(long long)B_WIN * NH * N_TOK * HD];
__device__ __half g_attn [(long long)M_ROWS * CH];            // [B,N,C] fp16
__device__ __half g_wqkvh[(long long)QKV_N * CH];             // [N=1536,K=512] K-major fp16
__device__ __half g_wprojh[(long long)CH * CH];               // [N=512, K=512] K-major fp16

// ---------------- PTX helpers ----------------
__device__ __forceinline__ void mma_f16(float c[4], const uint32_t a[4], const uint32_t b[2]) {
    asm volatile(
        "mma.sync.aligned.m16n8k16.row.col.f32.f16.f16.f32 "
        "{%0,%1,%2,%3}, {%4,%5,%6,%7}, {%8,%9}, {%0,%1,%2,%3};\n"
        : "+f"(c[0]), "+f"(c[1]), "+f"(c[2]), "+f"(c[3])
        : "r"(a[0]), "r"(a[1]), "r"(a[2]), "r"(a[3]),
          "r"(b[0]), "r"(b[1]));
}
__device__ __forceinline__ void cp_async16(void* smem, const void* gmem) {
    uint32_t s = (uint32_t)__cvta_generic_to_shared(smem);
    asm volatile("cp.async.cg.shared.global [%0], [%1], 16;\n" :: "r"(s), "l"(gmem));
}
__device__ __forceinline__ void cp_commit() { asm volatile("cp.async.commit_group;\n" ::: "memory"); }
__device__ __forceinline__ void cp_wait0()  { asm volatile("cp.async.wait_group 0;\n" ::: "memory"); }
__device__ __forceinline__ void cp_wait1()  { asm volatile("cp.async.wait_group 1;\n" ::: "memory"); }

// ---------------- fp16 GEMM: C[M,N] = A[M,512] * Bt[N,512]^T + bias[N] ------
// 128x128 tile, BK=32 (2 x k16 steps), 256 threads, 8 warps (2x4),
// warp tile 64x32 -> 4x4 m16n8k16. 2-stage cp.async double buffer.
// EPI==0: A=g_xh, Bt=g_wqkvh, scatter fp16 into g_q/g_k/g_v.
// EPI==1: A=g_attn, Bt=g_wprojh, f32 row-major store to Cout.
#define AS_H 40          // halves per smem row (pad: conflict-free fragment loads)
#define KT_CNT (CH / 32) // 16

template<int EPI>
__global__ __launch_bounds__(256, 1)
void gemm_h_kernel(const float* __restrict__ bias, float* __restrict__ Cout, int N)
{
    __shared__ __half As[2][128 * AS_H];
    __shared__ __half Bs[2][128 * AS_H];

    const __half* A  = (EPI == 0) ? g_xh   : g_attn;
    const __half* Bt = (EPI == 0) ? g_wqkvh : g_wprojh;

    const int tid  = threadIdx.x;
    const int lane = tid & 31;
    const int warp = tid >> 5;
    const int wm   = warp >> 2;      // 0..1
    const int wn   = warp & 3;       // 0..3
    const int bm   = blockIdx.y * 128;
    const int bn   = blockIdx.x * 128;
    const int grp  = lane >> 2;      // 0..7
    const int tig  = lane & 3;       // 0..3

    float acc[4][4][4];
    #pragma unroll
    for (int mt = 0; mt < 4; mt++)
        #pragma unroll
        for (int nt = 0; nt < 4; nt++)
            #pragma unroll
            for (int r = 0; r < 4; r++) acc[mt][nt][r] = 0.0f;

    auto load_stage = [&](int kt, int s) {
        #pragma unroll
        for (int i = 0; i < 2; i++) {
            int idx = tid + i * 256;         // 0..511
            int row = idx >> 2, seg = idx & 3;
            cp_async16(&As[s][row * AS_H + seg * 8],
                       A + (size_t)(bm + row) * CH + kt * 32 + seg * 8);
        }
        #pragma unroll
        for (int i = 0; i < 2; i++) {
            int idx = tid + i * 256;
            int row = idx >> 2, seg = idx & 3;
            cp_async16(&Bs[s][row * AS_H + seg * 8],
                       Bt + (size_t)(bn + row) * CH + kt * 32 + seg * 8);
        }
    };

    load_stage(0, 0);
    cp_commit();

    for (int kt = 0; kt < KT_CNT; kt++) {
        if (kt + 1 < KT_CNT) {
            load_stage(kt + 1, (kt + 1) & 1);
            cp_commit();
            cp_wait1();
        } else {
            cp_wait0();
        }
        __syncthreads();

        const int s = kt & 1;
        #pragma unroll
        for (int ks = 0; ks < 2; ks++) {
            const int k0 = ks * 16;          // half offset
            uint32_t af[4][4], bf[4][2];
            #pragma unroll
            for (int mt = 0; mt < 4; mt++) {
                int r = wm * 64 + mt * 16 + grp;
                af[mt][0] = *(const uint32_t*)&As[s][(r    ) * AS_H + k0 + 2 * tig    ];
                af[mt][1] = *(const uint32_t*)&As[s][(r + 8) * AS_H + k0 + 2 * tig    ];
                af[mt][2] = *(const uint32_t*)&As[s][(r    ) * AS_H + k0 + 2 * tig + 8];
                af[mt][3] = *(const uint32_t*)&As[s][(r + 8) * AS_H + k0 + 2 * tig + 8];
            }
            #pragma unroll
            for (int nt = 0; nt < 4; nt++) {
                int c = wn * 32 + nt * 8 + grp;
                bf[nt][0] = *(const uint32_t*)&Bs[s][c * AS_H + k0 + 2 * tig    ];
                bf[nt][1] = *(const uint32_t*)&Bs[s][c * AS_H + k0 + 2 * tig + 8];
            }
            #pragma unroll
            for (int mt = 0; mt < 4; mt++)
                #pragma unroll
                for (int nt = 0; nt < 4; nt++)
                    mma_f16(acc[mt][nt], af[mt], bf[nt]);
        }
        __syncthreads();
    }

    // -------- epilogue --------
    #pragma unroll
    for (int mt = 0; mt < 4; mt++) {
        #pragma unroll
        for (int rr = 0; rr < 2; rr++) {          // c-reg row half: grp / grp+8
            int row = bm + wm * 64 + mt * 16 + grp + rr * 8;
            int b   = row / N_TOK;
            int n   = row - b * N_TOK;
            #pragma unroll
            for (int nt = 0; nt < 4; nt++) {
                int col0 = bn + wn * 32 + nt * 8 + (tig << 1);  // even
                float v0 = acc[mt][nt][rr * 2 + 0] + bias[col0];
                float v1 = acc[mt][nt][rr * 2 + 1] + bias[col0 + 1];
                if (EPI == 0) {
                    int which = col0 >> 9;
                    int h     = (col0 >> 5) & 15;
                    int d     = col0 & 31;
                    __half* dst = (which == 0) ? g_q : ((which == 1) ? g_k : g_v);
                    dst += (((size_t)b * NH + h) * N_TOK + n) * HD + d;
                    *(__half2*)dst = __floats2half2_rn(v0, v1);
                } else {
                    *(float2*)&Cout[(size_t)row * N + col0] = make_float2(v0, v1);
                }
            }
        }
    }
}

// ---------------- converters ----------------
__global__ void cvt_x_kernel(const float4* __restrict__ src)   // x f32 -> g_xh fp16
{
    size_t i = (size_t)blockIdx.x * blockDim.x + threadIdx.x;  // one float4 = 4 elems
    float4 v = src[i];
    __half2 a = __floats2half2_rn(v.x, v.y);
    __half2 b = __floats2half2_rn(v.z, v.w);
    uint2 o = make_uint2(*(uint32_t*)&a, *(uint32_t*)&b);
    ((uint2*)g_xh)[i] = o;
}

// src[K][N] f32 -> dst[N][K] fp16 (W=0: w_qkv -> g_wqkvh, W=1: w_proj -> g_wprojh)
template<int W>
__global__ void transpose_cvt_kernel(const float* __restrict__ src, int K, int N)
{
    __half* dst = (W == 0) ? g_wqkvh : g_wprojh;
    __shared__ float t[32][33];
    int nx = blockIdx.x * 32, kx = blockIdx.y * 32;
    #pragma unroll
    for (int i = 0; i < 4; i++)
        t[threadIdx.y + 8 * i][threadIdx.x] =
            src[(size_t)(kx + threadIdx.y + 8 * i) * N + nx + threadIdx.x];
    __syncthreads();
    #pragma unroll
    for (int i = 0; i < 4; i++)
        dst[(size_t)(nx + threadIdx.y + 8 * i) * K + kx + threadIdx.x] =
            __float2half_rn(t[threadIdx.x][threadIdx.y + 8 * i]);
}

// ---------------- attention kernel: one block per (window, head) -----------
#define QS_STRIDE 36
#define SS_STRIDE 57

__global__ __launch_bounds__(64, 1)
void attn_kernel(const float* __restrict__ bias_table)
{
    const int h = blockIdx.x;
    const int w = blockIdx.y;
    const int t = threadIdx.x;

    __shared__ float qs[56 * QS_STRIDE];
    __shared__ float ks2[56 * QS_STRIDE];
    __shared__ float vs[56 * QS_STRIDE];
    __shared__ float ss[56 * SS_STRIDE];
    __shared__ float bs[169];

    for (int i = t; i < 169; i += 64) bs[i] = bias_table[i * NH + h];

    const size_t base = ((size_t)w * NH + h) * (N_TOK * HD);   // halves
    const uint2* q2 = (const uint2*)(g_q + base);              // 4 halves each
    const uint2* k2 = (const uint2*)(g_k + base);
    const uint2* v2 = (const uint2*)(g_v + base);
    for (int f = t; f < (N_TOK * HD) / 4; f += 64) {           // 392 quads
        int n  = f >> 3;
        int c4 = (f & 7) << 2;
        uint2 rq = q2[f], rk = k2[f], rv = v2[f];
        float2 a, b;
        a = __half22float2(*(__half2*)&rq.x); b = __half22float2(*(__half2*)&rq.y);
        *(float4*)&qs [n * QS_STRIDE + c4] = make_float4(a.x, a.y, b.x, b.y);
        a = __half22float2(*(__half2*)&rk.x); b = __half22float2(*(__half2*)&rk.y);
        *(float4*)&ks2[n * QS_STRIDE + c4] = make_float4(a.x, a.y, b.x, b.y);
        a = __half22float2(*(__half2*)&rv.x); b = __half22float2(*(__half2*)&rv.y);
        *(float4*)&vs [n * QS_STRIDE + c4] = make_float4(a.x, a.y, b.x, b.y);
    }
    for (int f = t; f < 56; f += 64) {
        int n  = 49 + (f >> 3);
        int c4 = (f & 7) << 2;
        float4 z = make_float4(0.f, 0.f, 0.f, 0.f);
        *(float4*)&qs [n * QS_STRIDE + c4] = z;
        *(float4*)&ks2[n * QS_STRIDE + c4] = z;
        *(float4*)&vs [n * QS_STRIDE + c4] = z;
    }
    __syncthreads();

    if (t < 49) {
        const int ti = t / 7;
        const int tj = t % 7;
        float a[8][8];
        #pragma unroll
        for (int i = 0; i < 8; i++)
            #pragma unroll
            for (int j = 0; j < 8; j++) a[i][j] = 0.f;

        #pragma unroll
        for (int kk = 0; kk < 8; kk++) {
            float4 kv[8];
            #pragma unroll
            for (int j = 0; j < 8; j++)
                kv[j] = *(const float4*)&ks2[(tj + 7 * j) * QS_STRIDE + kk * 4];
            #pragma unroll
            for (int i = 0; i < 8; i++) {
                float4 qv = *(const float4*)&qs[(ti + 7 * i) * QS_STRIDE + kk * 4];
                #pragma unroll
                for (int j = 0; j < 8; j++) {
                    a[i][j] += qv.x * kv[j].x;
                    a[i][j] += qv.y * kv[j].y;
                    a[i][j] += qv.z * kv[j].z;
                    a[i][j] += qv.w * kv[j].w;
                }
            }
        }
        const float scale = 0.04419417382415922f;   // 512^-0.5
        #pragma unroll
        for (int i = 0; i < 8; i++) {
            int n = ti + 7 * i;
            #pragma unroll
            for (int j = 0; j < 8; j++) {
                int m = tj + 7 * j;
                float v = a[i][j] * scale;
                if (n < 49 && m < 49)
                    v += bs[(i - j + 6) * 13 + (ti - tj + 6)];
                ss[n * SS_STRIDE + m] = v;
            }
        }
    }
    __syncthreads();

    if (t < 49) {
        float mx = -1e30f;
        for (int m = 0; m < 49; m++) mx = fmaxf(mx, ss[t * SS_STRIDE + m]);
        float sum = 0.f;
        for (int m = 0; m < 49; m++) {
            float e = __expf(ss[t * SS_STRIDE + m] - mx);
            sum += e;
            ss[t * SS_STRIDE + m] = e;
        }
        float inv = 1.f / sum;
        for (int m = 0; m < 49; m++) ss[t * SS_STRIDE + m] *= inv;
        for (int m = 49; m < 56; m++) ss[t * SS_STRIDE + m] = 0.f;
    }
    __syncthreads();

    if (t < 56) {
        const int ti = t >> 3;
        const int tc = t & 7;
        float4 o[8];
        #pragma unroll
        for (int i = 0; i < 8; i++) o[i] = make_float4(0.f, 0.f, 0.f, 0.f);

        for (int m = 0; m < 56; m++) {
            float4 vv = *(const float4*)&vs[m * QS_STRIDE + tc * 4];
            #pragma unroll
            for (int i = 0; i < 8; i++) {
                float p = ss[(ti + 7 * i) * SS_STRIDE + m];
                o[i].x += p * vv.x;
                o[i].y += p * vv.y;
                o[i].z += p * vv.z;
                o[i].w += p * vv.w;
            }
        }
        #pragma unroll
        for (int i = 0; i < 8; i++) {
            int n = ti + 7 * i;
            if (n < 49) {
                size_t off = ((size_t)w * N_TOK + n) * CH + h * HD + tc * 4;
                __half2 h0 = __floats2half2_rn(o[i].x, o[i].y);
                __half2 h1 = __floats2half2_rn(o[i].z, o[i].w);
                *(uint2*)(g_attn + off) = make_uint2(*(uint32_t*)&h0, *(uint32_t*)&h1);
            }
        }
    }
}

// ---------------- launch ----------------
extern "C" void kernel_launch(void* const* d_in, const int* in_sizes, int n_in,
                              void* d_out, int out_size)
{
    const float* x          = (const float*)d_in[0];
    const float* w_qkv      = (const float*)d_in[1];
    const float* b_qkv      = (const float*)d_in[2];
    const float* w_proj     = (const float*)d_in[3];
    const float* b_proj     = (const float*)d_in[4];
    const float* bias_table = (const float*)d_in[5];
    float* out = (float*)d_out;

    // converts (independent)
    cvt_x_kernel<<<(M_ROWS * CH / 4) / 256, 256>>>((const float4*)x);
    transpose_cvt_kernel<0><<<dim3(QKV_N / 32, CH / 32), dim3(32, 8)>>>(w_qkv, CH, QKV_N);
    transpose_cvt_kernel<1><<<dim3(CH / 32,    CH / 32), dim3(32, 8)>>>(w_proj, CH, CH);

    // K1: qkv = x @ w_qkv + b_qkv  -> scatter fp16 to g_q/g_k/g_v
    gemm_h_kernel<0><<<dim3(QKV_N / 128, M_ROWS / 128), 256>>>(b_qkv, nullptr, QKV_N);

    // K2: windowed attention -> g_attn [B,N,C] fp16
    attn_kernel<<<dim3(NH, B_WIN), 64>>>(bias_table);

    // K3: out = g_attn @ w_proj + b_proj
    gemm_h_kernel<1><<<dim3(CH / 128, M_ROWS / 128), 256>>>(b_proj, out, CH);
}

// round 5
// speedup vs baseline: 1.5294x; 1.0568x over previous
#include <cuda_runtime.h>
#include <cuda_fp16.h>
#include <cstdint>
#include <cstddef>

// ---------------- problem constants ----------------
#define B_WIN 4096
#define N_TOK 49
#define CH    512
#define NH    16
#define HD    32
#define M_ROWS (B_WIN * N_TOK)      // 200704
#define QKV_N  (3 * CH)             // 1536

// ---------------- scratch (static device globals; alloc-free rule) ----------
__device__ __half g_xh   [(long long)M_ROWS * CH];            // x in fp16
__device__ __half g_q    [(long long)B_WIN * NH * N_TOK * HD];// [B,H,N,hd] fp16
__device__ __half g_k    [(long long)B_WIN * NH * N_TOK * HD];
__device__ __half g_v    [(long long)B_WIN * NH * N_TOK * HD];
__device__ __half g_attn [(long long)M_ROWS * CH];            // [B,N,C] fp16
__device__ __half g_wqkvh[(long long)QKV_N * CH];             // [N=1536,K=512] K-major fp16
__device__ __half g_wprojh[(long long)CH * CH];               // [N=512, K=512] K-major fp16

// ---------------- PTX helpers ----------------
__device__ __forceinline__ void mma_f16(float c[4], const uint32_t a[4], const uint32_t b[2]) {
    asm volatile(
        "mma.sync.aligned.m16n8k16.row.col.f32.f16.f16.f32 "
        "{%0,%1,%2,%3}, {%4,%5,%6,%7}, {%8,%9}, {%0,%1,%2,%3};\n"
        : "+f"(c[0]), "+f"(c[1]), "+f"(c[2]), "+f"(c[3])
        : "r"(a[0]), "r"(a[1]), "r"(a[2]), "r"(a[3]),
          "r"(b[0]), "r"(b[1]));
}
__device__ __forceinline__ void cp_async16(void* smem, const void* gmem) {
    uint32_t s = (uint32_t)__cvta_generic_to_shared(smem);
    asm volatile("cp.async.cg.shared.global [%0], [%1], 16;\n" :: "r"(s), "l"(gmem));
}
__device__ __forceinline__ void cp_commit() { asm volatile("cp.async.commit_group;\n" ::: "memory"); }
__device__ __forceinline__ void cp_wait0()  { asm volatile("cp.async.wait_group 0;\n" ::: "memory"); }
__device__ __forceinline__ void cp_wait1()  { asm volatile("cp.async.wait_group 1;\n" ::: "memory"); }

// ---------------- fp16 GEMM: C[M,N] = A[M,512] * Bt[N,512]^T + bias[N] ------
// 128x128 tile, BK=32 (2 x k16 steps), 256 threads, 8 warps (2x4),
// warp tile 64x32 -> 4x4 m16n8k16. 2-stage cp.async double buffer.
// __launch_bounds__(256, 2): force 2 CTAs/SM (cross-CTA latency hiding).
#define AS_H 40          // halves per smem row (pad: conflict-free fragment loads)
#define KT_CNT (CH / 32) // 16

template<int EPI>
__global__ __launch_bounds__(256, 2)
void gemm_h_kernel(const float* __restrict__ bias, float* __restrict__ Cout, int N)
{
    __shared__ __half As[2][128 * AS_H];
    __shared__ __half Bs[2][128 * AS_H];

    const __half* A  = (EPI == 0) ? g_xh   : g_attn;
    const __half* Bt = (EPI == 0) ? g_wqkvh : g_wprojh;

    const int tid  = threadIdx.x;
    const int lane = tid & 31;
    const int warp = tid >> 5;
    const int wm   = warp >> 2;      // 0..1
    const int wn   = warp & 3;       // 0..3
    const int bm   = blockIdx.y * 128;
    const int bn   = blockIdx.x * 128;
    const int grp  = lane >> 2;      // 0..7
    const int tig  = lane & 3;       // 0..3

    float acc[4][4][4];
    #pragma unroll
    for (int mt = 0; mt < 4; mt++)
        #pragma unroll
        for (int nt = 0; nt < 4; nt++)
            #pragma unroll
            for (int r = 0; r < 4; r++) acc[mt][nt][r] = 0.0f;

    auto load_stage = [&](int kt, int s) {
        #pragma unroll
        for (int i = 0; i < 2; i++) {
            int idx = tid + i * 256;         // 0..511
            int row = idx >> 2, seg = idx & 3;
            cp_async16(&As[s][row * AS_H + seg * 8],
                       A + (size_t)(bm + row) * CH + kt * 32 + seg * 8);
        }
        #pragma unroll
        for (int i = 0; i < 2; i++) {
            int idx = tid + i * 256;
            int row = idx >> 2, seg = idx & 3;
            cp_async16(&Bs[s][row * AS_H + seg * 8],
                       Bt + (size_t)(bn + row) * CH + kt * 32 + seg * 8);
        }
    };

    load_stage(0, 0);
    cp_commit();

    for (int kt = 0; kt < KT_CNT; kt++) {
        if (kt + 1 < KT_CNT) {
            load_stage(kt + 1, (kt + 1) & 1);
            cp_commit();
            cp_wait1();
        } else {
            cp_wait0();
        }
        __syncthreads();

        const int s = kt & 1;
        #pragma unroll
        for (int ks = 0; ks < 2; ks++) {
            const int k0 = ks * 16;          // half offset
            uint32_t af[4][4], bf[4][2];
            #pragma unroll
            for (int mt = 0; mt < 4; mt++) {
                int r = wm * 64 + mt * 16 + grp;
                af[mt][0] = *(const uint32_t*)&As[s][(r    ) * AS_H + k0 + 2 * tig    ];
                af[mt][1] = *(const uint32_t*)&As[s][(r + 8) * AS_H + k0 + 2 * tig    ];
                af[mt][2] = *(const uint32_t*)&As[s][(r    ) * AS_H + k0 + 2 * tig + 8];
                af[mt][3] = *(const uint32_t*)&As[s][(r + 8) * AS_H + k0 + 2 * tig + 8];
            }
            #pragma unroll
            for (int nt = 0; nt < 4; nt++) {
                int c = wn * 32 + nt * 8 + grp;
                bf[nt][0] = *(const uint32_t*)&Bs[s][c * AS_H + k0 + 2 * tig    ];
                bf[nt][1] = *(const uint32_t*)&Bs[s][c * AS_H + k0 + 2 * tig + 8];
            }
            #pragma unroll
            for (int mt = 0; mt < 4; mt++)
                #pragma unroll
                for (int nt = 0; nt < 4; nt++)
                    mma_f16(acc[mt][nt], af[mt], bf[nt]);
        }
        __syncthreads();
    }

    // -------- epilogue --------
    #pragma unroll
    for (int mt = 0; mt < 4; mt++) {
        #pragma unroll
        for (int rr = 0; rr < 2; rr++) {          // c-reg row half: grp / grp+8
            int row = bm + wm * 64 + mt * 16 + grp + rr * 8;
            int b   = row / N_TOK;
            int n   = row - b * N_TOK;
            #pragma unroll
            for (int nt = 0; nt < 4; nt++) {
                int col0 = bn + wn * 32 + nt * 8 + (tig << 1);  // even
                float v0 = acc[mt][nt][rr * 2 + 0] + bias[col0];
                float v1 = acc[mt][nt][rr * 2 + 1] + bias[col0 + 1];
                if (EPI == 0) {
                    int which = col0 >> 9;
                    int h     = (col0 >> 5) & 15;
                    int d     = col0 & 31;
                    __half* dst = (which == 0) ? g_q : ((which == 1) ? g_k : g_v);
                    dst += (((size_t)b * NH + h) * N_TOK + n) * HD + d;
                    *(__half2*)dst = __floats2half2_rn(v0, v1);
                } else {
                    *(float2*)&Cout[(size_t)row * N + col0] = make_float2(v0, v1);
                }
            }
        }
    }
}

// ---------------- converters ----------------
__global__ void cvt_x_kernel(const float4* __restrict__ src)   // x f32 -> g_xh fp16
{
    size_t i = (size_t)blockIdx.x * blockDim.x + threadIdx.x;  // one float4 = 4 elems
    float4 v = src[i];
    __half2 a = __floats2half2_rn(v.x, v.y);
    __half2 b = __floats2half2_rn(v.z, v.w);
    uint2 o = make_uint2(*(uint32_t*)&a, *(uint32_t*)&b);
    ((uint2*)g_xh)[i] = o;
}

// src[K][N] f32 -> dst[N][K] fp16 (W=0: w_qkv -> g_wqkvh, W=1: w_proj -> g_wprojh)
template<int W>
__global__ void transpose_cvt_kernel(const float* __restrict__ src, int K, int N)
{
    __half* dst = (W == 0) ? g_wqkvh : g_wprojh;
    __shared__ float t[32][33];
    int nx = blockIdx.x * 32, kx = blockIdx.y * 32;
    #pragma unroll
    for (int i = 0; i < 4; i++)
        t[threadIdx.y + 8 * i][threadIdx.x] =
            src[(size_t)(kx + threadIdx.y + 8 * i) * N + nx + threadIdx.x];
    __syncthreads();
    #pragma unroll
    for (int i = 0; i < 4; i++)
        dst[(size_t)(nx + threadIdx.y + 8 * i) * K + kx + threadIdx.x] =
            __float2half_rn(t[threadIdx.x][threadIdx.y + 8 * i]);
}

// ---------------- attention kernel: one block per (window, head) -----------
// smem layout (floats): qs@0 (56*36), ks@2016 (56*36), vs@4032 (56*36),
//                       bs@6048 (169).  ss (56*57=3192) ALIASES qs+ks region
//                       (written only after all Q/K reads are fenced).
#define QS_STRIDE 36
#define SS_STRIDE 57
#define SM_FLOATS (6048 + 169)

__global__ __launch_bounds__(64, 9)
void attn_kernel(const float* __restrict__ bias_table)
{
    const int h = blockIdx.x;
    const int w = blockIdx.y;
    const int t = threadIdx.x;

    __shared__ float sm[SM_FLOATS];
    float* qs = sm;                 // 2016 floats
    float* ks2 = sm + 2016;         // 2016 floats
    float* vs = sm + 4032;          // 2016 floats
    float* bs = sm + 6048;          // 169 floats
    float* ss = sm;                 // 3192 floats, aliases qs+ks

    for (int i = t; i < 169; i += 64) bs[i] = bias_table[i * NH + h];

    const size_t base = ((size_t)w * NH + h) * (N_TOK * HD);   // halves
    const uint2* q2 = (const uint2*)(g_q + base);              // 4 halves each
    const uint2* k2 = (const uint2*)(g_k + base);
    const uint2* v2 = (const uint2*)(g_v + base);
    for (int f = t; f < (N_TOK * HD) / 4; f += 64) {           // 392 quads
        int n  = f >> 3;
        int c4 = (f & 7) << 2;
        uint2 rq = q2[f], rk = k2[f], rv = v2[f];
        float2 a, b;
        a = __half22float2(*(__half2*)&rq.x); b = __half22float2(*(__half2*)&rq.y);
        *(float4*)&qs [n * QS_STRIDE + c4] = make_float4(a.x, a.y, b.x, b.y);
        a = __half22float2(*(__half2*)&rk.x); b = __half22float2(*(__half2*)&rk.y);
        *(float4*)&ks2[n * QS_STRIDE + c4] = make_float4(a.x, a.y, b.x, b.y);
        a = __half22float2(*(__half2*)&rv.x); b = __half22float2(*(__half2*)&rv.y);
        *(float4*)&vs [n * QS_STRIDE + c4] = make_float4(a.x, a.y, b.x, b.y);
    }
    for (int f = t; f < 56; f += 64) {
        int n  = 49 + (f >> 3);
        int c4 = (f & 7) << 2;
        float4 z = make_float4(0.f, 0.f, 0.f, 0.f);
        *(float4*)&qs [n * QS_STRIDE + c4] = z;
        *(float4*)&ks2[n * QS_STRIDE + c4] = z;
        *(float4*)&vs [n * QS_STRIDE + c4] = z;
    }
    __syncthreads();

    // ---- S = Q K^T into registers (49 threads, 8x8 tiles, rows n=ti+7i) ----
    float a[8][8];
    const int ti = t / 7;
    const int tj = t % 7;
    if (t < 49) {
        #pragma unroll
        for (int i = 0; i < 8; i++)
            #pragma unroll
            for (int j = 0; j < 8; j++) a[i][j] = 0.f;

        #pragma unroll
        for (int kk = 0; kk < 8; kk++) {
            float4 kv[8];
            #pragma unroll
            for (int j = 0; j < 8; j++)
                kv[j] = *(const float4*)&ks2[(tj + 7 * j) * QS_STRIDE + kk * 4];
            #pragma unroll
            for (int i = 0; i < 8; i++) {
                float4 qv = *(const float4*)&qs[(ti + 7 * i) * QS_STRIDE + kk * 4];
                #pragma unroll
                for (int j = 0; j < 8; j++) {
                    a[i][j] += qv.x * kv[j].x;
                    a[i][j] += qv.y * kv[j].y;
                    a[i][j] += qv.z * kv[j].z;
                    a[i][j] += qv.w * kv[j].w;
                }
            }
        }
    }
    __syncthreads();   // all Q/K reads complete; ss may now overwrite qs/ks

    if (t < 49) {
        const float scale = 0.04419417382415922f;   // 512^-0.5
        #pragma unroll
        for (int i = 0; i < 8; i++) {
            int n = ti + 7 * i;
            #pragma unroll
            for (int j = 0; j < 8; j++) {
                int m = tj + 7 * j;
                float v = a[i][j] * scale;
                if (n < 49 && m < 49)
                    v += bs[(i - j + 6) * 13 + (ti - tj + 6)];
                ss[n * SS_STRIDE + m] = v;
            }
        }
    }
    __syncthreads();

    if (t < 49) {
        float mx = -1e30f;
        for (int m = 0; m < 49; m++) mx = fmaxf(mx, ss[t * SS_STRIDE + m]);
        float sum = 0.f;
        for (int m = 0; m < 49; m++) {
            float e = __expf(ss[t * SS_STRIDE + m] - mx);
            sum += e;
            ss[t * SS_STRIDE + m] = e;
        }
        float inv = 1.f / sum;
        for (int m = 0; m < 49; m++) ss[t * SS_STRIDE + m] *= inv;
        for (int m = 49; m < 56; m++) ss[t * SS_STRIDE + m] = 0.f;
    }
    __syncthreads();

    if (t < 56) {
        const int ri = t >> 3;
        const int tc = t & 7;
        float4 o[8];
        #pragma unroll
        for (int i = 0; i < 8; i++) o[i] = make_float4(0.f, 0.f, 0.f, 0.f);

        for (int m = 0; m < 56; m++) {
            float4 vv = *(const float4*)&vs[m * QS_STRIDE + tc * 4];
            #pragma unroll
            for (int i = 0; i < 8; i++) {
                float p = ss[(ri + 7 * i) * SS_STRIDE + m];
                o[i].x += p * vv.x;
                o[i].y += p * vv.y;
                o[i].z += p * vv.z;
                o[i].w += p * vv.w;
            }
        }
        #pragma unroll
        for (int i = 0; i < 8; i++) {
            int n = ri + 7 * i;
            if (n < 49) {
                size_t off = ((size_t)w * N_TOK + n) * CH + h * HD + tc * 4;
                __half2 h0 = __floats2half2_rn(o[i].x, o[i].y);
                __half2 h1 = __floats2half2_rn(o[i].z, o[i].w);
                *(uint2*)(g_attn + off) = make_uint2(*(uint32_t*)&h0, *(uint32_t*)&h1);
            }
        }
    }
}

// ---------------- launch ----------------
extern "C" void kernel_launch(void* const* d_in, const int* in_sizes, int n_in,
                              void* d_out, int out_size)
{
    const float* x          = (const float*)d_in[0];
    const float* w_qkv      = (const float*)d_in[1];
    const float* b_qkv      = (const float*)d_in[2];
    const float* w_proj     = (const float*)d_in[3];
    const float* b_proj     = (const float*)d_in[4];
    const float* bias_table = (const float*)d_in[5];
    float* out = (float*)d_out;

    // converts (independent)
    cvt_x_kernel<<<(M_ROWS * CH / 4) / 256, 256>>>((const float4*)x);
    transpose_cvt_kernel<0><<<dim3(QKV_N / 32, CH / 32), dim3(32, 8)>>>(w_qkv, CH, QKV_N);
    transpose_cvt_kernel<1><<<dim3(CH / 32,    CH / 32), dim3(32, 8)>>>(w_proj, CH, CH);

    // K1: qkv = x @ w_qkv + b_qkv  -> scatter fp16 to g_q/g_k/g_v
    gemm_h_kernel<0><<<dim3(QKV_N / 128, M_ROWS / 128), 256>>>(b_qkv, nullptr, QKV_N);

    // K2: windowed attention -> g_attn [B,N,C] fp16
    attn_kernel<<<dim3(NH, B_WIN), 64>>>(bias_table);

    // K3: out = g_attn @ w_proj + b_proj
    gemm_h_kernel<1><<<dim3(CH / 128, M_ROWS / 128), 256>>>(b_proj, out, CH);
}

// round 6
// speedup vs baseline: 1.5718x; 1.0277x over previous
#include <cuda_runtime.h>
#include <cuda_fp16.h>
#include <cstdint>
#include <cstddef>

// ---------------- problem constants ----------------
#define B_WIN 4096
#define N_TOK 49
#define CH    512
#define NH    16
#define HD    32
#define M_ROWS (B_WIN * N_TOK)      // 200704
#define QKV_N  (3 * CH)             // 1536

// ---------------- scratch (static device globals; alloc-free rule) ----------
__device__ __half g_xh   [(long long)M_ROWS * CH];            // x in fp16
__device__ __half g_q    [(long long)B_WIN * NH * N_TOK * HD];// [B,H,N,hd] fp16
__device__ __half g_k    [(long long)B_WIN * NH * N_TOK * HD];
__device__ __half g_v    [(long long)B_WIN * NH * N_TOK * HD];
__device__ __half g_attn [(long long)M_ROWS * CH];            // [B,N,C] fp16
__device__ __half g_wqkvh[(long long)QKV_N * CH];             // [N=1536,K=512] K-major fp16
__device__ __half g_wprojh[(long long)CH * CH];               // [N=512, K=512] K-major fp16

// ---------------- PTX helpers ----------------
__device__ __forceinline__ void mma_f16(float c[4], const uint32_t a[4], const uint32_t b[2]) {
    asm volatile(
        "mma.sync.aligned.m16n8k16.row.col.f32.f16.f16.f32 "
        "{%0,%1,%2,%3}, {%4,%5,%6,%7}, {%8,%9}, {%0,%1,%2,%3};\n"
        : "+f"(c[0]), "+f"(c[1]), "+f"(c[2]), "+f"(c[3])
        : "r"(a[0]), "r"(a[1]), "r"(a[2]), "r"(a[3]),
          "r"(b[0]), "r"(b[1]));
}
__device__ __forceinline__ void ldm_x4(uint32_t& r0, uint32_t& r1, uint32_t& r2, uint32_t& r3,
                                       uint32_t saddr) {
    asm volatile("ldmatrix.sync.aligned.m8n8.x4.shared.b16 {%0,%1,%2,%3}, [%4];"
                 : "=r"(r0), "=r"(r1), "=r"(r2), "=r"(r3) : "r"(saddr));
}
__device__ __forceinline__ void cp_async16(void* smem, const void* gmem) {
    uint32_t s = (uint32_t)__cvta_generic_to_shared(smem);
    asm volatile("cp.async.cg.shared.global [%0], [%1], 16;\n" :: "r"(s), "l"(gmem));
}
__device__ __forceinline__ void cp_commit() { asm volatile("cp.async.commit_group;\n" ::: "memory"); }
__device__ __forceinline__ void cp_wait0()  { asm volatile("cp.async.wait_group 0;\n" ::: "memory"); }
__device__ __forceinline__ void cp_wait1()  { asm volatile("cp.async.wait_group 1;\n" ::: "memory"); }

// fast exp on the FFMA pipe (avoids the 0.5 op/cyc/SM MUFU wall).
// exp(x) = 2^(x*log2e); n = rint(y) via magic add; 2^f degree-5 poly; 2^n via
// exponent-field add. Valid for x <= 0 (clamped at -80; exp(-80)~1.8e-35).
__device__ __forceinline__ float fast_exp(float x) {
    x = fmaxf(x, -80.0f);
    float y = x * 1.4426950408889634f;
    float t = y + 12582912.0f;                 // 1.5*2^23: round-to-nearest
    int   n = __float_as_int(t) - 0x4B400000;  // integer part
    float f = y - (t - 12582912.0f);           // f in [-0.5, 0.5]
    float p = 1.33335581e-3f;
    p = fmaf(p, f, 9.61812911e-3f);
    p = fmaf(p, f, 5.55041087e-2f);
    p = fmaf(p, f, 2.40226507e-1f);
    p = fmaf(p, f, 6.93147180e-1f);
    p = fmaf(p, f, 1.0f);
    return __int_as_float(__float_as_int(p) + (n << 23));
}

// ---------------- fp16 GEMM: C[M,N] = A[M,512] * Bt[N,512]^T + bias[N] ------
// 128x128 tile, BK=32 (2 x k16 steps), 256 threads, 8 warps (2x4),
// warp tile 64x32 -> 4x4 m16n8k16. 2-stage cp.async double buffer.
// Fragments via ldmatrix.x4 (6 per k-step vs 24 scalar LDS).
#define AS_H 40          // halves per smem row (80B: conflict-free ldmatrix phases)
#define KT_CNT (CH / 32) // 16

template<int EPI>
__global__ __launch_bounds__(256, 2)
void gemm_h_kernel(const float* __restrict__ bias, float* __restrict__ Cout, int N)
{
    __shared__ __half As[2][128 * AS_H];
    __shared__ __half Bs[2][128 * AS_H];

    const __half* A  = (EPI == 0) ? g_xh   : g_attn;
    const __half* Bt = (EPI == 0) ? g_wqkvh : g_wprojh;

    const int tid  = threadIdx.x;
    const int lane = tid & 31;
    const int warp = tid >> 5;
    const int wm   = warp >> 2;      // 0..1
    const int wn   = warp & 3;       // 0..3
    const int bm   = blockIdx.y * 128;
    const int bn   = blockIdx.x * 128;
    const int grp  = lane >> 2;      // 0..7
    const int tig  = lane & 3;       // 0..3

    // ldmatrix per-lane address components
    const int lg  = lane >> 3;       // matrix group 0..3
    const int lr  = lane & 7;        // row within 8
    const int a_row = (lg & 1) * 8 + lr;       // + wm*64 + mt*16
    const int a_k   = (lg >> 1) * 8;           // + k0
    const int b_row = (lg >> 1) * 8 + lr;      // + wn*32 + p*16
    const int b_k   = (lg & 1) * 8;            // + k0

    const uint32_t as_base[2] = {
        (uint32_t)__cvta_generic_to_shared(&As[0][0]),
        (uint32_t)__cvta_generic_to_shared(&As[1][0]) };
    const uint32_t bs_base[2] = {
        (uint32_t)__cvta_generic_to_shared(&Bs[0][0]),
        (uint32_t)__cvta_generic_to_shared(&Bs[1][0]) };

    float acc[4][4][4];
    #pragma unroll
    for (int mt = 0; mt < 4; mt++)
        #pragma unroll
        for (int nt = 0; nt < 4; nt++)
            #pragma unroll
            for (int r = 0; r < 4; r++) acc[mt][nt][r] = 0.0f;

    auto load_stage = [&](int kt, int s) {
        #pragma unroll
        for (int i = 0; i < 2; i++) {
            int idx = tid + i * 256;         // 0..511
            int row = idx >> 2, seg = idx & 3;
            cp_async16(&As[s][row * AS_H + seg * 8],
                       A + (size_t)(bm + row) * CH + kt * 32 + seg * 8);
        }
        #pragma unroll
        for (int i = 0; i < 2; i++) {
            int idx = tid + i * 256;
            int row = idx >> 2, seg = idx & 3;
            cp_async16(&Bs[s][row * AS_H + seg * 8],
                       Bt + (size_t)(bn + row) * CH + kt * 32 + seg * 8);
        }
    };

    load_stage(0, 0);
    cp_commit();

    for (int kt = 0; kt < KT_CNT; kt++) {
        if (kt + 1 < KT_CNT) {
            load_stage(kt + 1, (kt + 1) & 1);
            cp_commit();
            cp_wait1();
        } else {
            cp_wait0();
        }
        __syncthreads();

        const int s = kt & 1;
        #pragma unroll
        for (int ks = 0; ks < 2; ks++) {
            const int k0 = ks * 16;          // half offset
            uint32_t af[4][4], bf[4][2];
            #pragma unroll
            for (int mt = 0; mt < 4; mt++) {
                uint32_t addr = as_base[s] +
                    (uint32_t)(((wm * 64 + mt * 16 + a_row) * AS_H + k0 + a_k) * 2);
                ldm_x4(af[mt][0], af[mt][1], af[mt][2], af[mt][3], addr);
            }
            #pragma unroll
            for (int p = 0; p < 2; p++) {
                uint32_t addr = bs_base[s] +
                    (uint32_t)(((wn * 32 + p * 16 + b_row) * AS_H + k0 + b_k) * 2);
                ldm_x4(bf[2 * p][0], bf[2 * p][1], bf[2 * p + 1][0], bf[2 * p + 1][1], addr);
            }
            #pragma unroll
            for (int mt = 0; mt < 4; mt++)
                #pragma unroll
                for (int nt = 0; nt < 4; nt++)
                    mma_f16(acc[mt][nt], af[mt], bf[nt]);
        }
        __syncthreads();
    }

    // -------- epilogue --------
    #pragma unroll
    for (int mt = 0; mt < 4; mt++) {
        #pragma unroll
        for (int rr = 0; rr < 2; rr++) {          // c-reg row half: grp / grp+8
            int row = bm + wm * 64 + mt * 16 + grp + rr * 8;
            int b   = row / N_TOK;
            int n   = row - b * N_TOK;
            #pragma unroll
            for (int nt = 0; nt < 4; nt++) {
                int col0 = bn + wn * 32 + nt * 8 + (tig << 1);  // even
                float v0 = acc[mt][nt][rr * 2 + 0] + bias[col0];
                float v1 = acc[mt][nt][rr * 2 + 1] + bias[col0 + 1];
                if (EPI == 0) {
                    int which = col0 >> 9;
                    int h     = (col0 >> 5) & 15;
                    int d     = col0 & 31;
                    __half* dst = (which == 0) ? g_q : ((which == 1) ? g_k : g_v);
                    dst += (((size_t)b * NH + h) * N_TOK + n) * HD + d;
                    *(__half2*)dst = __floats2half2_rn(v0, v1);
                } else {
                    *(float2*)&Cout[(size_t)row * N + col0] = make_float2(v0, v1);
                }
            }
        }
    }
}

// ---------------- converters ----------------
__global__ void cvt_x_kernel(const float4* __restrict__ src)   // x f32 -> g_xh fp16
{
    size_t i = (size_t)blockIdx.x * blockDim.x + threadIdx.x;  // one float4 = 4 elems
    float4 v = src[i];
    __half2 a = __floats2half2_rn(v.x, v.y);
    __half2 b = __floats2half2_rn(v.z, v.w);
    uint2 o = make_uint2(*(uint32_t*)&a, *(uint32_t*)&b);
    ((uint2*)g_xh)[i] = o;
}

// src[K][N] f32 -> dst[N][K] fp16 (W=0: w_qkv -> g_wqkvh, W=1: w_proj -> g_wprojh)
template<int W>
__global__ void transpose_cvt_kernel(const float* __restrict__ src, int K, int N)
{
    __half* dst = (W == 0) ? g_wqkvh : g_wprojh;
    __shared__ float t[32][33];
    int nx = blockIdx.x * 32, kx = blockIdx.y * 32;
    #pragma unroll
    for (int i = 0; i < 4; i++)
        t[threadIdx.y + 8 * i][threadIdx.x] =
            src[(size_t)(kx + threadIdx.y + 8 * i) * N + nx + threadIdx.x];
    __syncthreads();
    #pragma unroll
    for (int i = 0; i < 4; i++)
        dst[(size_t)(nx + threadIdx.y + 8 * i) * K + kx + threadIdx.x] =
            __float2half_rn(t[threadIdx.x][threadIdx.y + 8 * i]);
}

// ---------------- attention kernel: one block per (window, head) -----------
// smem layout (floats): qs@0 (56*36), ks@2016 (56*36), vs@4032 (56*36),
//                       bs@6048 (169).  ss (56*57=3192) ALIASES qs+ks region.
#define QS_STRIDE 36
#define SS_STRIDE 57
#define SM_FLOATS (6048 + 169)

__global__ __launch_bounds__(64, 9)
void attn_kernel(const float* __restrict__ bias_table)
{
    const int h = blockIdx.x;
    const int w = blockIdx.y;
    const int t = threadIdx.x;

    __shared__ float sm[SM_FLOATS];
    float* qs = sm;                 // 2016 floats
    float* ks2 = sm + 2016;         // 2016 floats
    float* vs = sm + 4032;          // 2016 floats
    float* bs = sm + 6048;          // 169 floats
    float* ss = sm;                 // 3192 floats, aliases qs+ks

    for (int i = t; i < 169; i += 64) bs[i] = bias_table[i * NH + h];

    const size_t base = ((size_t)w * NH + h) * (N_TOK * HD);   // halves
    const uint2* q2 = (const uint2*)(g_q + base);              // 4 halves each
    const uint2* k2 = (const uint2*)(g_k + base);
    const uint2* v2 = (const uint2*)(g_v + base);
    for (int f = t; f < (N_TOK * HD) / 4; f += 64) {           // 392 quads
        int n  = f >> 3;
        int c4 = (f & 7) << 2;
        uint2 rq = q2[f], rk = k2[f], rv = v2[f];
        float2 a, b;
        a = __half22float2(*(__half2*)&rq.x); b = __half22float2(*(__half2*)&rq.y);
        *(float4*)&qs [n * QS_STRIDE + c4] = make_float4(a.x, a.y, b.x, b.y);
        a = __half22float2(*(__half2*)&rk.x); b = __half22float2(*(__half2*)&rk.y);
        *(float4*)&ks2[n * QS_STRIDE + c4] = make_float4(a.x, a.y, b.x, b.y);
        a = __half22float2(*(__half2*)&rv.x); b = __half22float2(*(__half2*)&rv.y);
        *(float4*)&vs [n * QS_STRIDE + c4] = make_float4(a.x, a.y, b.x, b.y);
    }
    for (int f = t; f < 56; f += 64) {
        int n  = 49 + (f >> 3);
        int c4 = (f & 7) << 2;
        float4 z = make_float4(0.f, 0.f, 0.f, 0.f);
        *(float4*)&qs [n * QS_STRIDE + c4] = z;
        *(float4*)&ks2[n * QS_STRIDE + c4] = z;
        *(float4*)&vs [n * QS_STRIDE + c4] = z;
    }
    __syncthreads();

    // ---- S = Q K^T into registers (49 threads, 8x8 tiles, rows n=ti+7i) ----
    float a[8][8];
    const int ti = t / 7;
    const int tj = t % 7;
    if (t < 49) {
        #pragma unroll
        for (int i = 0; i < 8; i++)
            #pragma unroll
            for (int j = 0; j < 8; j++) a[i][j] = 0.f;

        #pragma unroll
        for (int kk = 0; kk < 8; kk++) {
            float4 kv[8];
            #pragma unroll
            for (int j = 0; j < 8; j++)
                kv[j] = *(const float4*)&ks2[(tj + 7 * j) * QS_STRIDE + kk * 4];
            #pragma unroll
            for (int i = 0; i < 8; i++) {
                float4 qv = *(const float4*)&qs[(ti + 7 * i) * QS_STRIDE + kk * 4];
                #pragma unroll
                for (int j = 0; j < 8; j++) {
                    a[i][j] += qv.x * kv[j].x;
                    a[i][j] += qv.y * kv[j].y;
                    a[i][j] += qv.z * kv[j].z;
                    a[i][j] += qv.w * kv[j].w;
                }
            }
        }
    }
    __syncthreads();   // all Q/K reads complete; ss may now overwrite qs/ks

    if (t < 49) {
        const float scale = 0.04419417382415922f;   // 512^-0.5
        #pragma unroll
        for (int i = 0; i < 8; i++) {
            int n = ti + 7 * i;
            #pragma unroll
            for (int j = 0; j < 8; j++) {
                int m = tj + 7 * j;
                float v = a[i][j] * scale;
                if (n < 49 && m < 49)
                    v += bs[(i - j + 6) * 13 + (ti - tj + 6)];
                ss[n * SS_STRIDE + m] = v;
            }
        }
    }
    __syncthreads();

    if (t < 49) {
        float mx = -1e30f;
        for (int m = 0; m < 49; m++) mx = fmaxf(mx, ss[t * SS_STRIDE + m]);
        float sum = 0.f;
        for (int m = 0; m < 49; m++) {
            float e = fast_exp(ss[t * SS_STRIDE + m] - mx);
            sum += e;
            ss[t * SS_STRIDE + m] = e;
        }
        float inv = 1.f / sum;
        for (int m = 0; m < 49; m++) ss[t * SS_STRIDE + m] *= inv;
        for (int m = 49; m < 56; m++) ss[t * SS_STRIDE + m] = 0.f;
    }
    __syncthreads();

    if (t < 56) {
        const int ri = t >> 3;
        const int tc = t & 7;
        float4 o[8];
        #pragma unroll
        for (int i = 0; i < 8; i++) o[i] = make_float4(0.f, 0.f, 0.f, 0.f);

        for (int m = 0; m < 56; m++) {
            float4 vv = *(const float4*)&vs[m * QS_STRIDE + tc * 4];
            #pragma unroll
            for (int i = 0; i < 8; i++) {
                float p = ss[(ri + 7 * i) * SS_STRIDE + m];
                o[i].x += p * vv.x;
                o[i].y += p * vv.y;
                o[i].z += p * vv.z;
                o[i].w += p * vv.w;
            }
        }
        #pragma unroll
        for (int i = 0; i < 8; i++) {
            int n = ri + 7 * i;
            if (n < 49) {
                size_t off = ((size_t)w * N_TOK + n) * CH + h * HD + tc * 4;
                __half2 h0 = __floats2half2_rn(o[i].x, o[i].y);
                __half2 h1 = __floats2half2_rn(o[i].z, o[i].w);
                *(uint2*)(g_attn + off) = make_uint2(*(uint32_t*)&h0, *(uint32_t*)&h1);
            }
        }
    }
}

// ---------------- launch ----------------
extern "C" void kernel_launch(void* const* d_in, const int* in_sizes, int n_in,
                              void* d_out, int out_size)
{
    const float* x          = (const float*)d_in[0];
    const float* w_qkv      = (const float*)d_in[1];
    const float* b_qkv      = (const float*)d_in[2];
    const float* w_proj     = (const float*)d_in[3];
    const float* b_proj     = (const float*)d_in[4];
    const float* bias_table = (const float*)d_in[5];
    float* out = (float*)d_out;

    // converts (independent)
    cvt_x_kernel<<<(M_ROWS * CH / 4) / 256, 256>>>((const float4*)x);
    transpose_cvt_kernel<0><<<dim3(QKV_N / 32, CH / 32), dim3(32, 8)>>>(w_qkv, CH, QKV_N);
    transpose_cvt_kernel<1><<<dim3(CH / 32,    CH / 32), dim3(32, 8)>>>(w_proj, CH, CH);

    // K1: qkv = x @ w_qkv + b_qkv  -> scatter fp16 to g_q/g_k/g_v
    gemm_h_kernel<0><<<dim3(QKV_N / 128, M_ROWS / 128), 256>>>(b_qkv, nullptr, QKV_N);

    // K2: windowed attention -> g_attn [B,N,C] fp16
    attn_kernel<<<dim3(NH, B_WIN), 64>>>(bias_table);

    // K3: out = g_attn @ w_proj + b_proj
    gemm_h_kernel<1><<<dim3(CH / 128, M_ROWS / 128), 256>>>(b_proj, out, CH);
}

// round 8
// speedup vs baseline: 2.0942x; 1.3324x over previous
#include <cuda_runtime.h>
#include <cuda_fp16.h>
#include <cstdint>
#include <cstddef>

// ---------------- problem constants ----------------
#define B_WIN 4096
#define N_TOK 49
#define CH    512
#define NH    16
#define HD    32
#define M_ROWS (B_WIN * N_TOK)      // 200704
#define QKV_N  (3 * CH)             // 1536

// ---------------- scratch (static device globals; alloc-free rule) ----------
__device__ __half g_xh   [(long long)M_ROWS * CH];            // x in fp16
__device__ __half g_q    [(long long)B_WIN * NH * N_TOK * HD];// [B,H,N,hd] fp16
__device__ __half g_k    [(long long)B_WIN * NH * N_TOK * HD];
__device__ __half g_v    [(long long)B_WIN * NH * N_TOK * HD];
__device__ __half g_attn [(long long)M_ROWS * CH];            // [B,N,C] fp16
__device__ __half g_wqkvh[(long long)QKV_N * CH];             // [N=1536,K=512] K-major fp16
__device__ __half g_wprojh[(long long)CH * CH];               // [N=512, K=512] K-major fp16

// ---------------- PTX helpers ----------------
__device__ __forceinline__ void mma_f16(float c[4], const uint32_t a[4], const uint32_t b[2]) {
    asm volatile(
        "mma.sync.aligned.m16n8k16.row.col.f32.f16.f16.f32 "
        "{%0,%1,%2,%3}, {%4,%5,%6,%7}, {%8,%9}, {%0,%1,%2,%3};\n"
        : "+f"(c[0]), "+f"(c[1]), "+f"(c[2]), "+f"(c[3])
        : "r"(a[0]), "r"(a[1]), "r"(a[2]), "r"(a[3]),
          "r"(b[0]), "r"(b[1]));
}
__device__ __forceinline__ void ldm_x4(uint32_t& r0, uint32_t& r1, uint32_t& r2, uint32_t& r3,
                                       uint32_t saddr) {
    asm volatile("ldmatrix.sync.aligned.m8n8.x4.shared.b16 {%0,%1,%2,%3}, [%4];"
                 : "=r"(r0), "=r"(r1), "=r"(r2), "=r"(r3) : "r"(saddr));
}
__device__ __forceinline__ void cp_async16(void* smem, const void* gmem) {
    uint32_t s = (uint32_t)__cvta_generic_to_shared(smem);
    asm volatile("cp.async.cg.shared.global [%0], [%1], 16;\n" :: "r"(s), "l"(gmem));
}
__device__ __forceinline__ void cp_commit() { asm volatile("cp.async.commit_group;\n" ::: "memory"); }
__device__ __forceinline__ void cp_wait0()  { asm volatile("cp.async.wait_group 0;\n" ::: "memory"); }
__device__ __forceinline__ void cp_wait1()  { asm volatile("cp.async.wait_group 1;\n" ::: "memory"); }

// fast exp on the FFMA pipe. Valid for x <= 0 (clamped at -80).
__device__ __forceinline__ float fast_exp(float x) {
    x = fmaxf(x, -80.0f);
    float y = x * 1.4426950408889634f;
    float t = y + 12582912.0f;                 // 1.5*2^23: round-to-nearest
    int   n = __float_as_int(t) - 0x4B400000;  // integer part
    float f = y - (t - 12582912.0f);           // f in [-0.5, 0.5]
    float p = 1.33335581e-3f;
    p = fmaf(p, f, 9.61812911e-3f);
    p = fmaf(p, f, 5.55041087e-2f);
    p = fmaf(p, f, 2.40226507e-1f);
    p = fmaf(p, f, 6.93147180e-1f);
    p = fmaf(p, f, 1.0f);
    return __int_as_float(__float_as_int(p) + (n << 23));
}

// ---------------- fp16 GEMM (unchanged from round 6) -----------------------
#define AS_H 40
#define KT_CNT (CH / 32)

template<int EPI>
__global__ __launch_bounds__(256, 2)
void gemm_h_kernel(const float* __restrict__ bias, float* __restrict__ Cout, int N)
{
    __shared__ __half As[2][128 * AS_H];
    __shared__ __half Bs[2][128 * AS_H];

    const __half* A  = (EPI == 0) ? g_xh   : g_attn;
    const __half* Bt = (EPI == 0) ? g_wqkvh : g_wprojh;

    const int tid  = threadIdx.x;
    const int lane = tid & 31;
    const int warp = tid >> 5;
    const int wm   = warp >> 2;
    const int wn   = warp & 3;
    const int bm   = blockIdx.y * 128;
    const int bn   = blockIdx.x * 128;
    const int grp  = lane >> 2;
    const int tig  = lane & 3;

    const int lg  = lane >> 3;
    const int lr  = lane & 7;
    const int a_row = (lg & 1) * 8 + lr;
    const int a_k   = (lg >> 1) * 8;
    const int b_row = (lg >> 1) * 8 + lr;
    const int b_k   = (lg & 1) * 8;

    const uint32_t as_base[2] = {
        (uint32_t)__cvta_generic_to_shared(&As[0][0]),
        (uint32_t)__cvta_generic_to_shared(&As[1][0]) };
    const uint32_t bs_base[2] = {
        (uint32_t)__cvta_generic_to_shared(&Bs[0][0]),
        (uint32_t)__cvta_generic_to_shared(&Bs[1][0]) };

    float acc[4][4][4];
    #pragma unroll
    for (int mt = 0; mt < 4; mt++)
        #pragma unroll
        for (int nt = 0; nt < 4; nt++)
            #pragma unroll
            for (int r = 0; r < 4; r++) acc[mt][nt][r] = 0.0f;

    auto load_stage = [&](int kt, int s) {
        #pragma unroll
        for (int i = 0; i < 2; i++) {
            int idx = tid + i * 256;
            int row = idx >> 2, seg = idx & 3;
            cp_async16(&As[s][row * AS_H + seg * 8],
                       A + (size_t)(bm + row) * CH + kt * 32 + seg * 8);
        }
        #pragma unroll
        for (int i = 0; i < 2; i++) {
            int idx = tid + i * 256;
            int row = idx >> 2, seg = idx & 3;
            cp_async16(&Bs[s][row * AS_H + seg * 8],
                       Bt + (size_t)(bn + row) * CH + kt * 32 + seg * 8);
        }
    };

    load_stage(0, 0);
    cp_commit();

    for (int kt = 0; kt < KT_CNT; kt++) {
        if (kt + 1 < KT_CNT) {
            load_stage(kt + 1, (kt + 1) & 1);
            cp_commit();
            cp_wait1();
        } else {
            cp_wait0();
        }
        __syncthreads();

        const int s = kt & 1;
        #pragma unroll
        for (int ks = 0; ks < 2; ks++) {
            const int k0 = ks * 16;
            uint32_t af[4][4], bf[4][2];
            #pragma unroll
            for (int mt = 0; mt < 4; mt++) {
                uint32_t addr = as_base[s] +
                    (uint32_t)(((wm * 64 + mt * 16 + a_row) * AS_H + k0 + a_k) * 2);
                ldm_x4(af[mt][0], af[mt][1], af[mt][2], af[mt][3], addr);
            }
            #pragma unroll
            for (int p = 0; p < 2; p++) {
                uint32_t addr = bs_base[s] +
                    (uint32_t)(((wn * 32 + p * 16 + b_row) * AS_H + k0 + b_k) * 2);
                ldm_x4(bf[2 * p][0], bf[2 * p][1], bf[2 * p + 1][0], bf[2 * p + 1][1], addr);
            }
            #pragma unroll
            for (int mt = 0; mt < 4; mt++)
                #pragma unroll
                for (int nt = 0; nt < 4; nt++)
                    mma_f16(acc[mt][nt], af[mt], bf[nt]);
        }
        __syncthreads();
    }

    #pragma unroll
    for (int mt = 0; mt < 4; mt++) {
        #pragma unroll
        for (int rr = 0; rr < 2; rr++) {
            int row = bm + wm * 64 + mt * 16 + grp + rr * 8;
            int b   = row / N_TOK;
            int n   = row - b * N_TOK;
            #pragma unroll
            for (int nt = 0; nt < 4; nt++) {
                int col0 = bn + wn * 32 + nt * 8 + (tig << 1);
                float v0 = acc[mt][nt][rr * 2 + 0] + bias[col0];
                float v1 = acc[mt][nt][rr * 2 + 1] + bias[col0 + 1];
                if (EPI == 0) {
                    int which = col0 >> 9;
                    int h     = (col0 >> 5) & 15;
                    int d     = col0 & 31;
                    __half* dst = (which == 0) ? g_q : ((which == 1) ? g_k : g_v);
                    dst += (((size_t)b * NH + h) * N_TOK + n) * HD + d;
                    *(__half2*)dst = __floats2half2_rn(v0, v1);
                } else {
                    *(float2*)&Cout[(size_t)row * N + col0] = make_float2(v0, v1);
                }
            }
        }
    }
}

// ---------------- converters ----------------
__global__ void cvt_x_kernel(const float4* __restrict__ src)
{
    size_t i = (size_t)blockIdx.x * blockDim.x + threadIdx.x;
    float4 v = src[i];
    __half2 a = __floats2half2_rn(v.x, v.y);
    __half2 b = __floats2half2_rn(v.z, v.w);
    uint2 o = make_uint2(*(uint32_t*)&a, *(uint32_t*)&b);
    ((uint2*)g_xh)[i] = o;
}

template<int W>
__global__ void transpose_cvt_kernel(const float* __restrict__ src, int K, int N)
{
    __half* dst = (W == 0) ? g_wqkvh : g_wprojh;
    __shared__ float t[32][33];
    int nx = blockIdx.x * 32, kx = blockIdx.y * 32;
    #pragma unroll
    for (int i = 0; i < 4; i++)
        t[threadIdx.y + 8 * i][threadIdx.x] =
            src[(size_t)(kx + threadIdx.y + 8 * i) * N + nx + threadIdx.x];
    __syncthreads();
    #pragma unroll
    for (int i = 0; i < 4; i++)
        dst[(size_t)(nx + threadIdx.y + 8 * i) * K + kx + threadIdx.x] =
            __float2half_rn(t[threadIdx.x][threadIdx.y + 8 * i]);
}

// ---------------- tensor-core attention: one block per (window, head) ------
// 128 threads (4 warps). S = Q K^T (mma), softmax (unnormalized P fp16 + inv),
// O = P V (mma), scale by inv at store.
// smem bytes: hQ@0 [64][40]h, hK@5120 [64][40]h, hVt@10240 [32][72]h,
//             hP@14848 [64][72]h, fBs@24064 [169]f, fInv@24740 [49]f.
//             fS (f32, [49][51]) aliases hQ/hK region (dead after S mma).
#define AT_OFF_K   5120
#define AT_OFF_VT  10240
#define AT_OFF_P   14848
#define AT_OFF_BS  24064
#define AT_OFF_INV 24740
#define AT_SMEM    24960
#define S_ST 51     // odd stride: conflict-free row-wise softmax
#define V_ST 72

__global__ __launch_bounds__(128, 6)
void attn_mma_kernel(const float* __restrict__ bias_table)
{
    const int h  = blockIdx.x;
    const int wi = blockIdx.y;
    const int t  = threadIdx.x;
    const int warp = t >> 5;
    const int lane = t & 31;

    __shared__ __align__(16) char sm_raw[AT_SMEM];
    __half* hQ  = (__half*)(sm_raw);
    __half* hK  = (__half*)(sm_raw + AT_OFF_K);
    __half* hVt = (__half*)(sm_raw + AT_OFF_VT);
    __half* hP  = (__half*)(sm_raw + AT_OFF_P);
    float*  fBs = (float*)(sm_raw + AT_OFF_BS);
    float*  fInv= (float*)(sm_raw + AT_OFF_INV);
    float*  fS  = (float*)(sm_raw);                 // aliases hQ/hK

    for (int i = t; i < 169; i += 128) fBs[i] = bias_table[i * NH + h];

    const size_t base = ((size_t)wi * NH + h) * (N_TOK * HD);
    const uint4* gq = (const uint4*)(g_q + base);   // 8 halves per uint4
    const uint4* gk = (const uint4*)(g_k + base);
    const __half* gv = g_v + base;

    // Q, K: 49 rows x 32 halves = 196 uint4 each
    for (int f = t; f < 196; f += 128) {
        int n = f >> 2, sg = f & 3;
        *(uint4*)&hQ[n * 40 + sg * 8] = gq[f];
        *(uint4*)&hK[n * 40 + sg * 8] = gk[f];
    }
    // V transposed: hVt[d][m] = V[m][d]
    for (int idx = t; idx < N_TOK * HD; idx += 128) {
        int n = idx >> 5, d = idx & 31;
        hVt[d * V_ST + n] = gv[idx];
    }
    // zero Vt pad cols m=49..63 (required: multiplied by zero P cols)
    for (int idx = t; idx < 32 * 15; idx += 128) {
        int d = idx / 15, m = 49 + idx % 15;
        hVt[d * V_ST + m] = __ushort_as_half((unsigned short)0);
    }
    __syncthreads();

    // ---- S = Q K^T : warp handles rows 16*warp..16*warp+15 ----
    const int lg = lane >> 3, lr = lane & 7;
    const int a_row = (lg & 1) * 8 + lr;
    const int a_k   = (lg >> 1) * 8;
    const int b_row = (lg >> 1) * 8 + lr;
    const int b_k   = (lg & 1) * 8;
    const uint32_t qb  = (uint32_t)__cvta_generic_to_shared(hQ);
    const uint32_t kb  = (uint32_t)__cvta_generic_to_shared(hK);

    float sc[7][4];
    #pragma unroll
    for (int nt = 0; nt < 7; nt++)
        #pragma unroll
        for (int r = 0; r < 4; r++) sc[nt][r] = 0.f;

    #pragma unroll
    for (int ks = 0; ks < 2; ks++) {
        const int k0 = ks * 16;
        uint32_t af[4], bf[8][2];
        ldm_x4(af[0], af[1], af[2], af[3],
               qb + (uint32_t)(((16 * warp + a_row) * 40 + k0 + a_k) * 2));
        #pragma unroll
        for (int p = 0; p < 4; p++)
            ldm_x4(bf[2 * p][0], bf[2 * p][1], bf[2 * p + 1][0], bf[2 * p + 1][1],
                   kb + (uint32_t)(((p * 16 + b_row) * 40 + k0 + b_k) * 2));
        #pragma unroll
        for (int nt = 0; nt < 7; nt++)
            mma_f16(sc[nt], af, bf[nt]);
    }
    __syncthreads();   // all Q/K reads done; fS may overwrite

    // ---- write S*scale + bias (rows<49, cols<49) ----
    {
        const int grp = lane >> 2, tig = lane & 3;
        const float scale = 0.04419417382415922f;   // 512^-0.5
        #pragma unroll
        for (int rr = 0; rr < 2; rr++) {
            int r = 16 * warp + grp + 8 * rr;
            if (r < 49) {
                int rd = (r * 9363) >> 16;          // r/7
                int rm = r - rd * 7;
                #pragma unroll
                for (int nt = 0; nt < 7; nt++) {
                    #pragma unroll
                    for (int cc = 0; cc < 2; cc++) {
                        int m = nt * 8 + 2 * tig + cc;
                        if (m < 49) {
                            int md = (m * 9363) >> 16;
                            int mm = m - md * 7;
                            fS[r * S_ST + m] = sc[nt][rr * 2 + cc] * scale
                                             + fBs[(rd - md + 6) * 13 + (rm - mm + 6)];
                        }
                    }
                }
            }
        }
    }
    __syncthreads();

    // ---- softmax rows: unnormalized fp16 P + per-row inv ----
    if (t < 49) {
        float mx = -1e30f;
        #pragma unroll 7
        for (int m = 0; m < 49; m++) mx = fmaxf(mx, fS[t * S_ST + m]);
        float sum = 0.f;
        #pragma unroll 7
        for (int m = 0; m < 49; m++) {
            float e = fast_exp(fS[t * S_ST + m] - mx);
            sum += e;
            hP[t * V_ST + m] = __float2half_rn(e);
        }
        #pragma unroll
        for (int m = 49; m < 64; m++) hP[t * V_ST + m] = __ushort_as_half((unsigned short)0);
        fInv[t] = 1.f / sum;
    }
    __syncthreads();

    // ---- O = P V : warp rows 16*warp.., cols d 0..31 ----
    {
        const uint32_t pb = (uint32_t)__cvta_generic_to_shared(hP);
        const uint32_t vb = (uint32_t)__cvta_generic_to_shared(hVt);
        float oc[4][4];
        #pragma unroll
        for (int nt = 0; nt < 4; nt++)
            #pragma unroll
            for (int r = 0; r < 4; r++) oc[nt][r] = 0.f;

        #pragma unroll
        for (int ks = 0; ks < 4; ks++) {
            const int k0 = ks * 16;
            uint32_t af[4], bf[4][2];
            ldm_x4(af[0], af[1], af[2], af[3],
                   pb + (uint32_t)(((16 * warp + a_row) * V_ST + k0 + a_k) * 2));
            #pragma unroll
            for (int p = 0; p < 2; p++)
                ldm_x4(bf[2 * p][0], bf[2 * p][1], bf[2 * p + 1][0], bf[2 * p + 1][1],
                       vb + (uint32_t)(((p * 16 + b_row) * V_ST + k0 + b_k) * 2));
            #pragma unroll
            for (int nt = 0; nt < 4; nt++)
                mma_f16(oc[nt], af, bf[nt]);
        }

        const int grp = lane >> 2, tig = lane & 3;
        #pragma unroll
        for (int rr = 0; rr < 2; rr++) {
            int r = 16 * warp + grp + 8 * rr;
            if (r < 49) {
                float inv = fInv[r];
                size_t rowoff = ((size_t)wi * N_TOK + r) * CH + h * HD;
                #pragma unroll
                for (int nt = 0; nt < 4; nt++) {
                    int d = nt * 8 + 2 * tig;
                    __half2 o = __floats2half2_rn(oc[nt][rr * 2 + 0] * inv,
                                                  oc[nt][rr * 2 + 1] * inv);
                    *(__half2*)(g_attn + rowoff + d) = o;
                }
            }
        }
    }
}

// ---------------- launch ----------------
extern "C" void kernel_launch(void* const* d_in, const int* in_sizes, int n_in,
                              void* d_out, int out_size)
{
    const float* x          = (const float*)d_in[0];
    const float* w_qkv      = (const float*)d_in[1];
    const float* b_qkv      = (const float*)d_in[2];
    const float* w_proj     = (const float*)d_in[3];
    const float* b_proj     = (const float*)d_in[4];
    const float* bias_table = (const float*)d_in[5];
    float* out = (float*)d_out;

    cvt_x_kernel<<<(M_ROWS * CH / 4) / 256, 256>>>((const float4*)x);
    transpose_cvt_kernel<0><<<dim3(QKV_N / 32, CH / 32), dim3(32, 8)>>>(w_qkv, CH, QKV_N);
    transpose_cvt_kernel<1><<<dim3(CH / 32,    CH / 32), dim3(32, 8)>>>(w_proj, CH, CH);

    gemm_h_kernel<0><<<dim3(QKV_N / 128, M_ROWS / 128), 256>>>(b_qkv, nullptr, QKV_N);

    attn_mma_kernel<<<dim3(NH, B_WIN), 128>>>(bias_table);

    gemm_h_kernel<1><<<dim3(CH / 128, M_ROWS / 128), 256>>>(b_proj, out, CH);
}

// round 9
// speedup vs baseline: 2.2228x; 1.0614x over previous
#include <cuda_runtime.h>
#include <cuda_fp16.h>
#include <cstdint>
#include <cstddef>

// ---------------- problem constants ----------------
#define B_WIN 4096
#define N_TOK 49
#define CH    512
#define NH    16
#define HD    32
#define M_ROWS (B_WIN * N_TOK)      // 200704
#define QKV_N  (3 * CH)             // 1536

// ---------------- scratch (static device globals; alloc-free rule) ----------
__device__ __half g_xh   [(long long)M_ROWS * CH];            // x in fp16
__device__ __half g_q    [(long long)B_WIN * NH * N_TOK * HD];// [B,H,N,hd] fp16
__device__ __half g_k    [(long long)B_WIN * NH * N_TOK * HD];
__device__ __half g_v    [(long long)B_WIN * NH * N_TOK * HD];
__device__ __half g_attn [(long long)M_ROWS * CH];            // [B,N,C] fp16
__device__ __half g_wqkvh[(long long)QKV_N * CH];             // [N=1536,K=512] K-major fp16
__device__ __half g_wprojh[(long long)CH * CH];               // [N=512, K=512] K-major fp16

// ---------------- PTX helpers ----------------
__device__ __forceinline__ void mma_f16(float c[4], const uint32_t a[4], const uint32_t b[2]) {
    asm volatile(
        "mma.sync.aligned.m16n8k16.row.col.f32.f16.f16.f32 "
        "{%0,%1,%2,%3}, {%4,%5,%6,%7}, {%8,%9}, {%0,%1,%2,%3};\n"
        : "+f"(c[0]), "+f"(c[1]), "+f"(c[2]), "+f"(c[3])
        : "r"(a[0]), "r"(a[1]), "r"(a[2]), "r"(a[3]),
          "r"(b[0]), "r"(b[1]));
}
__device__ __forceinline__ void ldm_x4(uint32_t& r0, uint32_t& r1, uint32_t& r2, uint32_t& r3,
                                       uint32_t saddr) {
    asm volatile("ldmatrix.sync.aligned.m8n8.x4.shared.b16 {%0,%1,%2,%3}, [%4];"
                 : "=r"(r0), "=r"(r1), "=r"(r2), "=r"(r3) : "r"(saddr));
}
__device__ __forceinline__ void cp_async16(void* smem, const void* gmem) {
    uint32_t s = (uint32_t)__cvta_generic_to_shared(smem);
    asm volatile("cp.async.cg.shared.global [%0], [%1], 16;\n" :: "r"(s), "l"(gmem));
}
__device__ __forceinline__ void cp_commit() { asm volatile("cp.async.commit_group;\n" ::: "memory"); }
__device__ __forceinline__ void cp_wait0()  { asm volatile("cp.async.wait_group 0;\n" ::: "memory"); }
__device__ __forceinline__ void cp_wait1()  { asm volatile("cp.async.wait_group 1;\n" ::: "memory"); }

// fast exp on the FFMA pipe. Valid for x <= 0 (clamped at -80).
__device__ __forceinline__ float fast_exp(float x) {
    x = fmaxf(x, -80.0f);
    float y = x * 1.4426950408889634f;
    float t = y + 12582912.0f;                 // 1.5*2^23: round-to-nearest
    int   n = __float_as_int(t) - 0x4B400000;  // integer part
    float f = y - (t - 12582912.0f);           // f in [-0.5, 0.5]
    float p = 1.33335581e-3f;
    p = fmaf(p, f, 9.61812911e-3f);
    p = fmaf(p, f, 5.55041087e-2f);
    p = fmaf(p, f, 2.40226507e-1f);
    p = fmaf(p, f, 6.93147180e-1f);
    p = fmaf(p, f, 1.0f);
    return __int_as_float(__float_as_int(p) + (n << 23));
}

// ---------------- fp16 GEMM: 3-stage cp.async ring, ONE sync/iter ----------
// 128x128 tile, BK=32 (2 x k16), 256 threads, 8 warps (2x4), warp tile 64x32.
#define AS_H 40
#define KT_CNT (CH / 32)            // 16
#define STAGE_H (128 * AS_H)        // halves per operand per stage
#define GEMM_DSM (3 * 2 * STAGE_H * 2)   // 61440 bytes

template<int EPI>
__global__ __launch_bounds__(256, 2)
void gemm_h_kernel(const float* __restrict__ bias, float* __restrict__ Cout, int N)
{
    extern __shared__ __half dsm[];   // [3 stages][As 128*40 | Bs 128*40]

    const __half* A  = (EPI == 0) ? g_xh   : g_attn;
    const __half* Bt = (EPI == 0) ? g_wqkvh : g_wprojh;

    const int tid  = threadIdx.x;
    const int lane = tid & 31;
    const int warp = tid >> 5;
    const int wm   = warp >> 2;
    const int wn   = warp & 3;
    const int bm   = blockIdx.y * 128;
    const int bn   = blockIdx.x * 128;
    const int grp  = lane >> 2;
    const int tig  = lane & 3;

    const int lg  = lane >> 3;
    const int lr  = lane & 7;
    const int a_row = (lg & 1) * 8 + lr;
    const int a_k   = (lg >> 1) * 8;
    const int b_row = (lg >> 1) * 8 + lr;
    const int b_k   = (lg & 1) * 8;

    const uint32_t sm_base = (uint32_t)__cvta_generic_to_shared(dsm);

    float acc[4][4][4];
    #pragma unroll
    for (int mt = 0; mt < 4; mt++)
        #pragma unroll
        for (int nt = 0; nt < 4; nt++)
            #pragma unroll
            for (int r = 0; r < 4; r++) acc[mt][nt][r] = 0.0f;

    auto load_stage = [&](int kt, int s) {
        __half* As = dsm + s * 2 * STAGE_H;
        __half* Bs = As + STAGE_H;
        #pragma unroll
        for (int i = 0; i < 2; i++) {
            int idx = tid + i * 256;
            int row = idx >> 2, seg = idx & 3;
            cp_async16(&As[row * AS_H + seg * 8],
                       A + (size_t)(bm + row) * CH + kt * 32 + seg * 8);
        }
        #pragma unroll
        for (int i = 0; i < 2; i++) {
            int idx = tid + i * 256;
            int row = idx >> 2, seg = idx & 3;
            cp_async16(&Bs[row * AS_H + seg * 8],
                       Bt + (size_t)(bn + row) * CH + kt * 32 + seg * 8);
        }
        cp_commit();
    };

    load_stage(0, 0);
    load_stage(1, 1);

    #pragma unroll 1
    for (int kt = 0; kt < KT_CNT; kt++) {
        if (kt == KT_CNT - 1) cp_wait0(); else cp_wait1();
        __syncthreads();                       // stage kt ready; compute kt-1 done everywhere
        if (kt + 2 < KT_CNT) load_stage(kt + 2, (kt + 2) % 3);

        const int s = kt % 3;
        const uint32_t as0 = sm_base + (uint32_t)(s * 2 * STAGE_H * 2);
        const uint32_t bs0 = as0 + STAGE_H * 2;
        #pragma unroll
        for (int ks = 0; ks < 2; ks++) {
            const int k0 = ks * 16;
            uint32_t af[4][4], bf[4][2];
            #pragma unroll
            for (int mt = 0; mt < 4; mt++) {
                uint32_t addr = as0 +
                    (uint32_t)(((wm * 64 + mt * 16 + a_row) * AS_H + k0 + a_k) * 2);
                ldm_x4(af[mt][0], af[mt][1], af[mt][2], af[mt][3], addr);
            }
            #pragma unroll
            for (int p = 0; p < 2; p++) {
                uint32_t addr = bs0 +
                    (uint32_t)(((wn * 32 + p * 16 + b_row) * AS_H + k0 + b_k) * 2);
                ldm_x4(bf[2 * p][0], bf[2 * p][1], bf[2 * p + 1][0], bf[2 * p + 1][1], addr);
            }
            #pragma unroll
            for (int mt = 0; mt < 4; mt++)
                #pragma unroll
                for (int nt = 0; nt < 4; nt++)
                    mma_f16(acc[mt][nt], af[mt], bf[nt]);
        }
    }

    // -------- epilogue --------
    #pragma unroll
    for (int mt = 0; mt < 4; mt++) {
        #pragma unroll
        for (int rr = 0; rr < 2; rr++) {
            int row = bm + wm * 64 + mt * 16 + grp + rr * 8;
            int b   = row / N_TOK;
            int n   = row - b * N_TOK;
            #pragma unroll
            for (int nt = 0; nt < 4; nt++) {
                int col0 = bn + wn * 32 + nt * 8 + (tig << 1);
                float v0 = acc[mt][nt][rr * 2 + 0] + bias[col0];
                float v1 = acc[mt][nt][rr * 2 + 1] + bias[col0 + 1];
                if (EPI == 0) {
                    int which = col0 >> 9;
                    int h     = (col0 >> 5) & 15;
                    int d     = col0 & 31;
                    __half* dst = (which == 0) ? g_q : ((which == 1) ? g_k : g_v);
                    dst += (((size_t)b * NH + h) * N_TOK + n) * HD + d;
                    *(__half2*)dst = __floats2half2_rn(v0, v1);
                } else {
                    *(float2*)&Cout[(size_t)row * N + col0] = make_float2(v0, v1);
                }
            }
        }
    }
}

// ---------------- converters ----------------
__global__ void cvt_x_kernel(const float4* __restrict__ src)
{
    size_t i = (size_t)blockIdx.x * blockDim.x + threadIdx.x;
    float4 v = src[i];
    __half2 a = __floats2half2_rn(v.x, v.y);
    __half2 b = __floats2half2_rn(v.z, v.w);
    uint2 o = make_uint2(*(uint32_t*)&a, *(uint32_t*)&b);
    ((uint2*)g_xh)[i] = o;
}

template<int W>
__global__ void transpose_cvt_kernel(const float* __restrict__ src, int K, int N)
{
    __half* dst = (W == 0) ? g_wqkvh : g_wprojh;
    __shared__ float t[32][33];
    int nx = blockIdx.x * 32, kx = blockIdx.y * 32;
    #pragma unroll
    for (int i = 0; i < 4; i++)
        t[threadIdx.y + 8 * i][threadIdx.x] =
            src[(size_t)(kx + threadIdx.y + 8 * i) * N + nx + threadIdx.x];
    __syncthreads();
    #pragma unroll
    for (int i = 0; i < 4; i++)
        dst[(size_t)(nx + threadIdx.y + 8 * i) * K + kx + threadIdx.x] =
            __float2half_rn(t[threadIdx.x][threadIdx.y + 8 * i]);
}

// ---------------- tensor-core attention, register softmax ------------------
// 128 threads (4 warps), one (window, head) per block.
// smem: hQ@0 [64][40]h, hK@5120 [64][40]h, hVt@10240 [32][72]h,
//       hP@14848 [64][72]h, fBs@24064 [169]f.
#define AT_OFF_K   5120
#define AT_OFF_VT  10240
#define AT_OFF_P   14848
#define AT_OFF_BS  24064
#define AT_SMEM    24744
#define V_ST 72

__global__ __launch_bounds__(128, 6)
void attn_mma_kernel(const float* __restrict__ bias_table)
{
    const int h  = blockIdx.x;
    const int wi = blockIdx.y;
    const int t  = threadIdx.x;
    const int warp = t >> 5;
    const int lane = t & 31;

    __shared__ __align__(16) char sm_raw[AT_SMEM];
    __half* hQ  = (__half*)(sm_raw);
    __half* hK  = (__half*)(sm_raw + AT_OFF_K);
    __half* hVt = (__half*)(sm_raw + AT_OFF_VT);
    __half* hP  = (__half*)(sm_raw + AT_OFF_P);
    float*  fBs = (float*)(sm_raw + AT_OFF_BS);

    for (int i = t; i < 169; i += 128) fBs[i] = bias_table[i * NH + h];

    const size_t base = ((size_t)wi * NH + h) * (N_TOK * HD);
    const uint4* gq = (const uint4*)(g_q + base);
    const uint4* gk = (const uint4*)(g_k + base);
    const __half* gv = g_v + base;

    for (int f = t; f < 196; f += 128) {       // Q,K: 49 rows x 32 halves
        int n = f >> 2, sg = f & 3;
        *(uint4*)&hQ[n * 40 + sg * 8] = gq[f];
        *(uint4*)&hK[n * 40 + sg * 8] = gk[f];
    }
    for (int idx = t; idx < N_TOK * HD; idx += 128) {   // Vt[d][m] = V[m][d]
        int n = idx >> 5, d = idx & 31;
        hVt[d * V_ST + n] = gv[idx];
    }
    for (int idx = t; idx < 32 * 15; idx += 128) {      // zero Vt pad cols
        int d = idx / 15, m = 49 + idx % 15;
        hVt[d * V_ST + m] = __ushort_as_half((unsigned short)0);
    }
    __syncthreads();

    // ---- S = Q K^T : warp handles rows 16*warp..+15 ----
    const int lg = lane >> 3, lr = lane & 7;
    const int a_row = (lg & 1) * 8 + lr;
    const int a_k   = (lg >> 1) * 8;
    const int b_row = (lg >> 1) * 8 + lr;
    const int b_k   = (lg & 1) * 8;
    const uint32_t qb = (uint32_t)__cvta_generic_to_shared(hQ);
    const uint32_t kb = (uint32_t)__cvta_generic_to_shared(hK);

    float sc[7][4];
    #pragma unroll
    for (int nt = 0; nt < 7; nt++)
        #pragma unroll
        for (int r = 0; r < 4; r++) sc[nt][r] = 0.f;

    #pragma unroll
    for (int ks = 0; ks < 2; ks++) {
        const int k0 = ks * 16;
        uint32_t af[4], bf[8][2];
        ldm_x4(af[0], af[1], af[2], af[3],
               qb + (uint32_t)(((16 * warp + a_row) * 40 + k0 + a_k) * 2));
        #pragma unroll
        for (int p = 0; p < 4; p++)
            ldm_x4(bf[2 * p][0], bf[2 * p][1], bf[2 * p + 1][0], bf[2 * p + 1][1],
                   kb + (uint32_t)(((p * 16 + b_row) * 40 + k0 + b_k) * 2));
        #pragma unroll
        for (int nt = 0; nt < 7; nt++)
            mma_f16(sc[nt], af, bf[nt]);
    }

    // ---- register softmax (quad = one row; shfl over tig lanes) ----
    const int grp = lane >> 2, tig = lane & 3;
    const float scale = 0.04419417382415922f;   // 512^-0.5
    float inv[2];
    #pragma unroll
    for (int rr = 0; rr < 2; rr++) {
        int r  = 16 * warp + grp + 8 * rr;
        int rc = min(r, 48);                    // clamp garbage rows: bounded bias idx
        int rd = (rc * 9363) >> 16;             // rc/7
        int rm = rc - rd * 7;
        float sv[7][2];
        float mx = -1e30f;
        #pragma unroll
        for (int nt = 0; nt < 7; nt++) {
            #pragma unroll
            for (int cc = 0; cc < 2; cc++) {
                int m = nt * 8 + 2 * tig + cc;
                float v = -1e30f;
                if (m < 49) {
                    int md = (m * 9363) >> 16;
                    int mm = m - md * 7;
                    v = sc[nt][rr * 2 + cc] * scale
                      + fBs[(rd - md + 6) * 13 + (rm - mm + 6)];
                }
                sv[nt][cc] = v;
                mx = fmaxf(mx, v);
            }
        }
        mx = fmaxf(mx, __shfl_xor_sync(0xffffffffu, mx, 1));
        mx = fmaxf(mx, __shfl_xor_sync(0xffffffffu, mx, 2));
        float sum = 0.f;
        #pragma unroll
        for (int nt = 0; nt < 7; nt++) {
            float e0 = fast_exp(sv[nt][0] - mx);
            float e1 = fast_exp(sv[nt][1] - mx);
            sum += e0 + e1;
            *(__half2*)&hP[r * V_ST + nt * 8 + 2 * tig] = __floats2half2_rn(e0, e1);
        }
        sum += __shfl_xor_sync(0xffffffffu, sum, 1);
        sum += __shfl_xor_sync(0xffffffffu, sum, 2);
        inv[rr] = 1.f / sum;
    }
    // zero hP pad cols 56..63 (k-dim of PV covers 0..63)
    {
        int r = t >> 1;
        int c = 56 + (t & 1) * 4;
        *(uint2*)&hP[r * V_ST + c] = make_uint2(0u, 0u);
    }
    __syncthreads();

    // ---- O = P V : warp rows 16*warp.., cols d 0..31 ----
    {
        const uint32_t pb = (uint32_t)__cvta_generic_to_shared(hP);
        const uint32_t vb = (uint32_t)__cvta_generic_to_shared(hVt);
        float oc[4][4];
        #pragma unroll
        for (int nt = 0; nt < 4; nt++)
            #pragma unroll
            for (int r = 0; r < 4; r++) oc[nt][r] = 0.f;

        #pragma unroll
        for (int ks = 0; ks < 4; ks++) {
            const int k0 = ks * 16;
            uint32_t af[4], bf[4][2];
            ldm_x4(af[0], af[1], af[2], af[3],
                   pb + (uint32_t)(((16 * warp + a_row) * V_ST + k0 + a_k) * 2));
            #pragma unroll
            for (int p = 0; p < 2; p++)
                ldm_x4(bf[2 * p][0], bf[2 * p][1], bf[2 * p + 1][0], bf[2 * p + 1][1],
                       vb + (uint32_t)(((p * 16 + b_row) * V_ST + k0 + b_k) * 2));
            #pragma unroll
            for (int nt = 0; nt < 4; nt++)
                mma_f16(oc[nt], af, bf[nt]);
        }

        #pragma unroll
        for (int rr = 0; rr < 2; rr++) {
            int r = 16 * warp + grp + 8 * rr;
            if (r < 49) {
                size_t rowoff = ((size_t)wi * N_TOK + r) * CH + h * HD;
                #pragma unroll
                for (int nt = 0; nt < 4; nt++) {
                    int d = nt * 8 + 2 * tig;
                    __half2 o = __floats2half2_rn(oc[nt][rr * 2 + 0] * inv[rr],
                                                  oc[nt][rr * 2 + 1] * inv[rr]);
                    *(__half2*)(g_attn + rowoff + d) = o;
                }
            }
        }
    }
}

// ---------------- launch ----------------
extern "C" void kernel_launch(void* const* d_in, const int* in_sizes, int n_in,
                              void* d_out, int out_size)
{
    const float* x          = (const float*)d_in[0];
    const float* w_qkv      = (const float*)d_in[1];
    const float* b_qkv      = (const float*)d_in[2];
    const float* w_proj     = (const float*)d_in[3];
    const float* b_proj     = (const float*)d_in[4];
    const float* bias_table = (const float*)d_in[5];
    float* out = (float*)d_out;

    cudaFuncSetAttribute(gemm_h_kernel<0>, cudaFuncAttributeMaxDynamicSharedMemorySize, GEMM_DSM);
    cudaFuncSetAttribute(gemm_h_kernel<1>, cudaFuncAttributeMaxDynamicSharedMemorySize, GEMM_DSM);

    cvt_x_kernel<<<(M_ROWS * CH / 4) / 256, 256>>>((const float4*)x);
    transpose_cvt_kernel<0><<<dim3(QKV_N / 32, CH / 32), dim3(32, 8)>>>(w_qkv, CH, QKV_N);
    transpose_cvt_kernel<1><<<dim3(CH / 32,    CH / 32), dim3(32, 8)>>>(w_proj, CH, CH);

    gemm_h_kernel<0><<<dim3(QKV_N / 128, M_ROWS / 128), 256, GEMM_DSM>>>(b_qkv, nullptr, QKV_N);

    attn_mma_kernel<<<dim3(NH, B_WIN), 128>>>(bias_table);

    gemm_h_kernel<1><<<dim3(CH / 128, M_ROWS / 128), 256, GEMM_DSM>>>(b_proj, out, CH);
}

// round 10
// speedup vs baseline: 2.3678x; 1.0652x over previous
#include <cuda_runtime.h>
#include <cuda_fp16.h>
#include <cstdint>
#include <cstddef>

// ---------------- problem constants ----------------
#define B_WIN 4096
#define N_TOK 49
#define CH    512
#define NH    16
#define HD    32
#define M_ROWS (B_WIN * N_TOK)      // 200704
#define QKV_N  (3 * CH)             // 1536

// ---------------- scratch (static device globals; alloc-free rule) ----------
__device__ __half g_xh   [(long long)M_ROWS * CH];            // x in fp16
__device__ __half g_q    [(long long)B_WIN * NH * N_TOK * HD];// [B,H,N,hd] fp16
__device__ __half g_k    [(long long)B_WIN * NH * N_TOK * HD];
__device__ __half g_v    [(long long)B_WIN * NH * N_TOK * HD];
__device__ __half g_attn [(long long)M_ROWS * CH];            // [B,N,C] fp16
__device__ __half g_wqkvh[(long long)QKV_N * CH];             // [N=1536,K=512] K-major fp16
__device__ __half g_wprojh[(long long)CH * CH];               // [N=512, K=512] K-major fp16

// ---------------- PTX helpers ----------------
__device__ __forceinline__ void mma_f16(float c[4], const uint32_t a[4], const uint32_t b[2]) {
    asm volatile(
        "mma.sync.aligned.m16n8k16.row.col.f32.f16.f16.f32 "
        "{%0,%1,%2,%3}, {%4,%5,%6,%7}, {%8,%9}, {%0,%1,%2,%3};\n"
        : "+f"(c[0]), "+f"(c[1]), "+f"(c[2]), "+f"(c[3])
        : "r"(a[0]), "r"(a[1]), "r"(a[2]), "r"(a[3]),
          "r"(b[0]), "r"(b[1]));
}
__device__ __forceinline__ void ldm_x4(uint32_t& r0, uint32_t& r1, uint32_t& r2, uint32_t& r3,
                                       uint32_t saddr) {
    asm volatile("ldmatrix.sync.aligned.m8n8.x4.shared.b16 {%0,%1,%2,%3}, [%4];"
                 : "=r"(r0), "=r"(r1), "=r"(r2), "=r"(r3) : "r"(saddr));
}
__device__ __forceinline__ void cp_async16(void* smem, const void* gmem) {
    uint32_t s = (uint32_t)__cvta_generic_to_shared(smem);
    asm volatile("cp.async.cg.shared.global [%0], [%1], 16;\n" :: "r"(s), "l"(gmem));
}
__device__ __forceinline__ void cp_commit() { asm volatile("cp.async.commit_group;\n" ::: "memory"); }
__device__ __forceinline__ void cp_wait0()  { asm volatile("cp.async.wait_group 0;\n" ::: "memory"); }

// fast exp on the FFMA pipe. Valid for x <= 0 (clamped at -80).
__device__ __forceinline__ float fast_exp(float x) {
    x = fmaxf(x, -80.0f);
    float y = x * 1.4426950408889634f;
    float t = y + 12582912.0f;                 // 1.5*2^23: round-to-nearest
    int   n = __float_as_int(t) - 0x4B400000;  // integer part
    float f = y - (t - 12582912.0f);           // f in [-0.5, 0.5]
    float p = 1.33335581e-3f;
    p = fmaf(p, f, 9.61812911e-3f);
    p = fmaf(p, f, 5.55041087e-2f);
    p = fmaf(p, f, 2.40226507e-1f);
    p = fmaf(p, f, 6.93147180e-1f);
    p = fmaf(p, f, 1.0f);
    return __int_as_float(__float_as_int(p) + (n << 23));
}

// ---------------- fp16 GEMM: BK=64, 2-stage ring, ONE sync/iter ------------
// 128x128 tile, BK=64 (4 x k16), 256 threads, 8 warps (2x4), warp tile 64x32.
#define AS_H 72                      // 64 + 8 pad (144B rows: conflict-free ldm)
#define KT_CNT (CH / 64)             // 8
#define STAGE_H (128 * AS_H)         // halves per operand per stage
#define GEMM_DSM (2 * 2 * STAGE_H * 2)   // 73728 bytes

template<int EPI>
__global__ __launch_bounds__(256, 2)
void gemm_h_kernel(const float* __restrict__ bias, float* __restrict__ Cout, int N)
{
    extern __shared__ __half dsm[];   // [2 stages][As 128*72 | Bs 128*72]

    const __half* A  = (EPI == 0) ? g_xh   : g_attn;
    const __half* Bt = (EPI == 0) ? g_wqkvh : g_wprojh;

    const int tid  = threadIdx.x;
    const int lane = tid & 31;
    const int warp = tid >> 5;
    const int wm   = warp >> 2;
    const int wn   = warp & 3;
    const int bm   = blockIdx.y * 128;
    const int bn   = blockIdx.x * 128;
    const int grp  = lane >> 2;
    const int tig  = lane & 3;

    const int lg  = lane >> 3;
    const int lr  = lane & 7;
    const int a_row = (lg & 1) * 8 + lr;
    const int a_k   = (lg >> 1) * 8;
    const int b_row = (lg >> 1) * 8 + lr;
    const int b_k   = (lg & 1) * 8;

    const uint32_t sm_base = (uint32_t)__cvta_generic_to_shared(dsm);

    float acc[4][4][4];
    #pragma unroll
    for (int mt = 0; mt < 4; mt++)
        #pragma unroll
        for (int nt = 0; nt < 4; nt++)
            #pragma unroll
            for (int r = 0; r < 4; r++) acc[mt][nt][r] = 0.0f;

    auto load_stage = [&](int kt, int s) {
        __half* As = dsm + s * 2 * STAGE_H;
        __half* Bs = As + STAGE_H;
        #pragma unroll
        for (int i = 0; i < 4; i++) {
            int idx = tid + i * 256;            // 0..1023
            int row = idx >> 3, seg = idx & 7;
            cp_async16(&As[row * AS_H + seg * 8],
                       A + (size_t)(bm + row) * CH + kt * 64 + seg * 8);
        }
        #pragma unroll
        for (int i = 0; i < 4; i++) {
            int idx = tid + i * 256;
            int row = idx >> 3, seg = idx & 7;
            cp_async16(&Bs[row * AS_H + seg * 8],
                       Bt + (size_t)(bn + row) * CH + kt * 64 + seg * 8);
        }
        cp_commit();
    };

    load_stage(0, 0);

    #pragma unroll 1
    for (int kt = 0; kt < KT_CNT; kt++) {
        cp_wait0();                            // stage kt loaded
        __syncthreads();                       // + compute kt-1 done everywhere
        if (kt + 1 < KT_CNT) load_stage(kt + 1, (kt + 1) & 1);

        const int s = kt & 1;
        const uint32_t as0 = sm_base + (uint32_t)(s * 2 * STAGE_H * 2);
        const uint32_t bs0 = as0 + STAGE_H * 2;
        #pragma unroll
        for (int ks = 0; ks < 4; ks++) {
            const int k0 = ks * 16;
            uint32_t af[4][4], bf[4][2];
            #pragma unroll
            for (int mt = 0; mt < 4; mt++) {
                uint32_t addr = as0 +
                    (uint32_t)(((wm * 64 + mt * 16 + a_row) * AS_H + k0 + a_k) * 2);
                ldm_x4(af[mt][0], af[mt][1], af[mt][2], af[mt][3], addr);
            }
            #pragma unroll
            for (int p = 0; p < 2; p++) {
                uint32_t addr = bs0 +
                    (uint32_t)(((wn * 32 + p * 16 + b_row) * AS_H + k0 + b_k) * 2);
                ldm_x4(bf[2 * p][0], bf[2 * p][1], bf[2 * p + 1][0], bf[2 * p + 1][1], addr);
            }
            #pragma unroll
            for (int mt = 0; mt < 4; mt++)
                #pragma unroll
                for (int nt = 0; nt < 4; nt++)
                    mma_f16(acc[mt][nt], af[mt], bf[nt]);
        }
    }

    // -------- epilogue --------
    #pragma unroll
    for (int mt = 0; mt < 4; mt++) {
        #pragma unroll
        for (int rr = 0; rr < 2; rr++) {
            int row = bm + wm * 64 + mt * 16 + grp + rr * 8;
            int b   = row / N_TOK;
            int n   = row - b * N_TOK;
            #pragma unroll
            for (int nt = 0; nt < 4; nt++) {
                int col0 = bn + wn * 32 + nt * 8 + (tig << 1);
                float v0 = acc[mt][nt][rr * 2 + 0] + bias[col0];
                float v1 = acc[mt][nt][rr * 2 + 1] + bias[col0 + 1];
                if (EPI == 0) {
                    int which = col0 >> 9;
                    int h     = (col0 >> 5) & 15;
                    int d     = col0 & 31;
                    __half* dst = (which == 0) ? g_q : ((which == 1) ? g_k : g_v);
                    dst += (((size_t)b * NH + h) * N_TOK + n) * HD + d;
                    *(__half2*)dst = __floats2half2_rn(v0, v1);
                } else {
                    *(float2*)&Cout[(size_t)row * N + col0] = make_float2(v0, v1);
                }
            }
        }
    }
}

// ---------------- converters ----------------
__global__ void cvt_x_kernel(const float4* __restrict__ src)
{
    size_t i = (size_t)blockIdx.x * blockDim.x + threadIdx.x;
    float4 v = src[i];
    __half2 a = __floats2half2_rn(v.x, v.y);
    __half2 b = __floats2half2_rn(v.z, v.w);
    uint2 o = make_uint2(*(uint32_t*)&a, *(uint32_t*)&b);
    ((uint2*)g_xh)[i] = o;
}

template<int W>
__global__ void transpose_cvt_kernel(const float* __restrict__ src, int K, int N)
{
    __half* dst = (W == 0) ? g_wqkvh : g_wprojh;
    __shared__ float t[32][33];
    int nx = blockIdx.x * 32, kx = blockIdx.y * 32;
    #pragma unroll
    for (int i = 0; i < 4; i++)
        t[threadIdx.y + 8 * i][threadIdx.x] =
            src[(size_t)(kx + threadIdx.y + 8 * i) * N + nx + threadIdx.x];
    __syncthreads();
    #pragma unroll
    for (int i = 0; i < 4; i++)
        dst[(size_t)(nx + threadIdx.y + 8 * i) * K + kx + threadIdx.x] =
            __float2half_rn(t[threadIdx.x][threadIdx.y + 8 * i]);
}

// ---------------- tensor-core attention, register softmax, warp-local ------
// 128 threads (4 warps), one (window, head) per block. After the single load
// barrier, each warp is fully independent (softmax + PV read only its rows).
#define AT_OFF_K   5120
#define AT_OFF_VT  10240
#define AT_OFF_P   14848
#define AT_OFF_BS  24064
#define AT_SMEM    24744
#define V_ST 72

__global__ __launch_bounds__(128, 6)
void attn_mma_kernel(const float* __restrict__ bias_table)
{
    const int h  = blockIdx.x;
    const int wi = blockIdx.y;
    const int t  = threadIdx.x;
    const int warp = t >> 5;
    const int lane = t & 31;

    __shared__ __align__(16) char sm_raw[AT_SMEM];
    __half* hQ  = (__half*)(sm_raw);
    __half* hK  = (__half*)(sm_raw + AT_OFF_K);
    __half* hVt = (__half*)(sm_raw + AT_OFF_VT);
    __half* hP  = (__half*)(sm_raw + AT_OFF_P);
    float*  fBs = (float*)(sm_raw + AT_OFF_BS);

    for (int i = t; i < 169; i += 128) fBs[i] = bias_table[i * NH + h];

    const size_t base = ((size_t)wi * NH + h) * (N_TOK * HD);
    const uint4* gq = (const uint4*)(g_q + base);
    const uint4* gk = (const uint4*)(g_k + base);
    const __half* gv = g_v + base;

    for (int f = t; f < 196; f += 128) {       // Q,K: 49 rows x 32 halves
        int n = f >> 2, sg = f & 3;
        *(uint4*)&hQ[n * 40 + sg * 8] = gq[f];
        *(uint4*)&hK[n * 40 + sg * 8] = gk[f];
    }
    for (int idx = t; idx < N_TOK * HD; idx += 128) {   // Vt[d][m] = V[m][d]
        int n = idx >> 5, d = idx & 31;
        hVt[d * V_ST + n] = gv[idx];
    }
    for (int idx = t; idx < 32 * 15; idx += 128) {      // zero Vt pad cols
        int d = idx / 15, m = 49 + idx % 15;
        hVt[d * V_ST + m] = __ushort_as_half((unsigned short)0);
    }
    __syncthreads();   // the ONLY block barrier

    // ---- S = Q K^T : warp handles rows 16*warp..+15 ----
    const int lg = lane >> 3, lr = lane & 7;
    const int a_row = (lg & 1) * 8 + lr;
    const int a_k   = (lg >> 1) * 8;
    const int b_row = (lg >> 1) * 8 + lr;
    const int b_k   = (lg & 1) * 8;
    const uint32_t qb = (uint32_t)__cvta_generic_to_shared(hQ);
    const uint32_t kb = (uint32_t)__cvta_generic_to_shared(hK);

    float sc[7][4];
    #pragma unroll
    for (int nt = 0; nt < 7; nt++)
        #pragma unroll
        for (int r = 0; r < 4; r++) sc[nt][r] = 0.f;

    #pragma unroll
    for (int ks = 0; ks < 2; ks++) {
        const int k0 = ks * 16;
        uint32_t af[4], bf[8][2];
        ldm_x4(af[0], af[1], af[2], af[3],
               qb + (uint32_t)(((16 * warp + a_row) * 40 + k0 + a_k) * 2));
        #pragma unroll
        for (int p = 0; p < 4; p++)
            ldm_x4(bf[2 * p][0], bf[2 * p][1], bf[2 * p + 1][0], bf[2 * p + 1][1],
                   kb + (uint32_t)(((p * 16 + b_row) * 40 + k0 + b_k) * 2));
        #pragma unroll
        for (int nt = 0; nt < 7; nt++)
            mma_f16(sc[nt], af, bf[nt]);
    }

    // ---- register softmax (quad = one row; shfl over tig lanes) ----
    const int grp = lane >> 2, tig = lane & 3;
    const float scale = 0.04419417382415922f;   // 512^-0.5
    float inv[2];
    #pragma unroll
    for (int rr = 0; rr < 2; rr++) {
        int r  = 16 * warp + grp + 8 * rr;
        int rc = min(r, 48);                    // clamp garbage rows: bounded bias idx
        int rd = (rc * 9363) >> 16;             // rc/7
        int rm = rc - rd * 7;
        float sv[7][2];
        float mx = -1e30f;
        #pragma unroll
        for (int nt = 0; nt < 7; nt++) {
            #pragma unroll
            for (int cc = 0; cc < 2; cc++) {
                int m = nt * 8 + 2 * tig + cc;
                float v = -1e30f;
                if (m < 49) {
                    int md = (m * 9363) >> 16;
                    int mm = m - md * 7;
                    v = sc[nt][rr * 2 + cc] * scale
                      + fBs[(rd - md + 6) * 13 + (rm - mm + 6)];
                }
                sv[nt][cc] = v;
                mx = fmaxf(mx, v);
            }
        }
        mx = fmaxf(mx, __shfl_xor_sync(0xffffffffu, mx, 1));
        mx = fmaxf(mx, __shfl_xor_sync(0xffffffffu, mx, 2));
        float sum = 0.f;
        #pragma unroll
        for (int nt = 0; nt < 7; nt++) {
            float e0 = fast_exp(sv[nt][0] - mx);
            float e1 = fast_exp(sv[nt][1] - mx);
            sum += e0 + e1;
            *(__half2*)&hP[r * V_ST + nt * 8 + 2 * tig] = __floats2half2_rn(e0, e1);
        }
        sum += __shfl_xor_sync(0xffffffffu, sum, 1);
        sum += __shfl_xor_sync(0xffffffffu, sum, 2);
        inv[rr] = 1.f / sum;
    }
    // zero this warp's hP pad cols 56..63 (rows 16*warp..+15)
    {
        int r = 16 * warp + (lane >> 1);
        int c = 56 + (lane & 1) * 4;
        *(uint2*)&hP[r * V_ST + c] = make_uint2(0u, 0u);
    }
    __syncwarp();      // hP rows for this warp visible to its own ldmatrix

    // ---- O = P V : warp rows 16*warp.. (A = its OWN hP rows), cols 0..31 ----
    {
        const uint32_t pb = (uint32_t)__cvta_generic_to_shared(hP);
        const uint32_t vb = (uint32_t)__cvta_generic_to_shared(hVt);
        float oc[4][4];
        #pragma unroll
        for (int nt = 0; nt < 4; nt++)
            #pragma unroll
            for (int r = 0; r < 4; r++) oc[nt][r] = 0.f;

        #pragma unroll
        for (int ks = 0; ks < 4; ks++) {
            const int k0 = ks * 16;
            uint32_t af[4], bf[4][2];
            ldm_x4(af[0], af[1], af[2], af[3],
                   pb + (uint32_t)(((16 * warp + a_row) * V_ST + k0 + a_k) * 2));
            #pragma unroll
            for (int p = 0; p < 2; p++)
                ldm_x4(bf[2 * p][0], bf[2 * p][1], bf[2 * p + 1][0], bf[2 * p + 1][1],
                       vb + (uint32_t)(((p * 16 + b_row) * V_ST + k0 + b_k) * 2));
            #pragma unroll
            for (int nt = 0; nt < 4; nt++)
                mma_f16(oc[nt], af, bf[nt]);
        }

        #pragma unroll
        for (int rr = 0; rr < 2; rr++) {
            int r = 16 * warp + grp + 8 * rr;
            if (r < 49) {
                size_t rowoff = ((size_t)wi * N_TOK + r) * CH + h * HD;
                #pragma unroll
                for (int nt = 0; nt < 4; nt++) {
                    int d = nt * 8 + 2 * tig;
                    __half2 o = __floats2half2_rn(oc[nt][rr * 2 + 0] * inv[rr],
                                                  oc[nt][rr * 2 + 1] * inv[rr]);
                    *(__half2*)(g_attn + rowoff + d) = o;
                }
            }
        }
    }
}

// ---------------- launch ----------------
extern "C" void kernel_launch(void* const* d_in, const int* in_sizes, int n_in,
                              void* d_out, int out_size)
{
    const float* x          = (const float*)d_in[0];
    const float* w_qkv      = (const float*)d_in[1];
    const float* b_qkv      = (const float*)d_in[2];
    const float* w_proj     = (const float*)d_in[3];
    const float* b_proj     = (const float*)d_in[4];
    const float* bias_table = (const float*)d_in[5];
    float* out = (float*)d_out;

    cudaFuncSetAttribute(gemm_h_kernel<0>, cudaFuncAttributeMaxDynamicSharedMemorySize, GEMM_DSM);
    cudaFuncSetAttribute(gemm_h_kernel<1>, cudaFuncAttributeMaxDynamicSharedMemorySize, GEMM_DSM);

    cvt_x_kernel<<<(M_ROWS * CH / 4) / 256, 256>>>((const float4*)x);
    transpose_cvt_kernel<0><<<dim3(QKV_N / 32, CH / 32), dim3(32, 8)>>>(w_qkv, CH, QKV_N);
    transpose_cvt_kernel<1><<<dim3(CH / 32,    CH / 32), dim3(32, 8)>>>(w_proj, CH, CH);

    gemm_h_kernel<0><<<dim3(QKV_N / 128, M_ROWS / 128), 256, GEMM_DSM>>>(b_qkv, nullptr, QKV_N);

    attn_mma_kernel<<<dim3(NH, B_WIN), 128>>>(bias_table);

    gemm_h_kernel<1><<<dim3(CH / 128, M_ROWS / 128), 256, GEMM_DSM>>>(b_proj, out, CH);
}